// round 1
// baseline (speedup 1.0000x reference)
#include <cuda_runtime.h>
#include <cstdint>

#define DIMN 896
#define NKEYS 585   // 8 self + 65 ad + 512 task

// ---------------- scratch (static device globals; no allocation) -----------
__device__ float  g_Q   [512   * 896];
__device__ float  g_Ks  [512   * 896];
__device__ float  g_Vs  [512   * 896];
__device__ float  g_Had [4160  * 896];
__device__ float  g_Ka  [4160  * 896];
__device__ float  g_Va  [4160  * 896];
__device__ float  g_Kt  [32768 * 896];
__device__ float  g_Vt  [32768 * 896];
__device__ float  g_attn[512   * 896];
__device__ float  g_y   [512   * 896];
__device__ float  g_yn  [512   * 896];
__device__ float2 g_rope[512 * 112];

// ---------------- RoPE table: cos/sin(pos * inv[d%56]) ---------------------
__global__ void rope_init_k() {
    int i = blockIdx.x * blockDim.x + threadIdx.x;
    if (i >= 512 * 112) return;
    int pos = i / 112, d = i % 112, f = d % 56;
    float inv = powf(10000.0f, -((float)(2 * f) / 112.0f));
    float ang = (float)pos * inv;
    g_rope[i] = make_float2(cosf(ang), sinf(ang));
}

// ---------------- build h_ad = concat(h_a, p) along seq --------------------
__global__ void build_had_k(const float* __restrict__ h_a, const float* __restrict__ p) {
    int i = blockIdx.x * blockDim.x + threadIdx.x;   // float4 index
    if (i >= 4160 * 224) return;
    int row = i / 224, c4 = i % 224;
    int b = row / 65, l = row % 65;
    const float4* src = (l < 64)
        ? (const float4*)(h_a + ((size_t)(b * 64 + l)) * 896)
        : (const float4*)(p   + (size_t)b * 896);
    ((float4*)(g_Had + (size_t)row * 896))[c4] = src[c4];
}

// ---------------- fp32 SGEMM: C[M,896] = A[M,896] @ B[896,896] + epi -------
// epi: 0 = +bias; 1 = +bias then RoPE(ropeL); 2 = +bias + residual; 3 = +bias, ReLU
__global__ __launch_bounds__(256, 2) void sgemm_k(
    const float* __restrict__ A, const float* __restrict__ B,
    const float* __restrict__ bias, float* __restrict__ C,
    int M, int epi, int ropeL, const float* __restrict__ res)
{
    constexpr int BK = 8, BM = 128, BN = 128;
    __shared__ float As[2][BK][BM];
    __shared__ float Bs[2][BK][BN];

    const int tid  = threadIdx.x;
    const int tx   = tid & 15, ty = tid >> 4;
    const int row0 = blockIdx.y * BM, col0 = blockIdx.x * BN;
    const int arow = tid >> 1, acol = (tid & 1) * 4;
    const int brow = tid >> 5, bcol = (tid & 31) * 4;

    float acc[8][8];
    #pragma unroll
    for (int i = 0; i < 8; i++)
        #pragma unroll
        for (int j = 0; j < 8; j++) acc[i][j] = 0.0f;

    // preload tile 0
    {
        float4 a4 = make_float4(0.f, 0.f, 0.f, 0.f);
        int gr = row0 + arow;
        if (gr < M) a4 = *(const float4*)(A + (size_t)gr * DIMN + acol);
        As[0][acol + 0][arow] = a4.x; As[0][acol + 1][arow] = a4.y;
        As[0][acol + 2][arow] = a4.z; As[0][acol + 3][arow] = a4.w;
        float4 b4 = *(const float4*)(B + (size_t)brow * DIMN + col0 + bcol);
        *(float4*)&Bs[0][brow][bcol] = b4;
    }
    __syncthreads();

    const int nk = DIMN / BK;  // 112
    int cbuf = 0;
    for (int t = 0; t < nk; t++) {
        float4 a4, b4;
        const bool hn = (t + 1 < nk);
        if (hn) {
            int kt = (t + 1) * BK;
            int gr = row0 + arow;
            a4 = make_float4(0.f, 0.f, 0.f, 0.f);
            if (gr < M) a4 = *(const float4*)(A + (size_t)gr * DIMN + kt + acol);
            b4 = *(const float4*)(B + (size_t)(kt + brow) * DIMN + col0 + bcol);
        }
        #pragma unroll
        for (int kk = 0; kk < BK; kk++) {
            float af[8], bf[8];
            *(float4*)&af[0] = *(const float4*)&As[cbuf][kk][ty * 8];
            *(float4*)&af[4] = *(const float4*)&As[cbuf][kk][ty * 8 + 4];
            *(float4*)&bf[0] = *(const float4*)&Bs[cbuf][kk][tx * 8];
            *(float4*)&bf[4] = *(const float4*)&Bs[cbuf][kk][tx * 8 + 4];
            #pragma unroll
            for (int i = 0; i < 8; i++)
                #pragma unroll
                for (int j = 0; j < 8; j++)
                    acc[i][j] = fmaf(af[i], bf[j], acc[i][j]);
        }
        if (hn) {
            int nb = cbuf ^ 1;
            As[nb][acol + 0][arow] = a4.x; As[nb][acol + 1][arow] = a4.y;
            As[nb][acol + 2][arow] = a4.z; As[nb][acol + 3][arow] = a4.w;
            *(float4*)&Bs[nb][brow][bcol] = b4;
        }
        __syncthreads();
        cbuf ^= 1;
    }

    // epilogue
    #pragma unroll
    for (int i = 0; i < 8; i++) {
        int gr = row0 + ty * 8 + i;
        if (gr >= M) continue;
        float* crow = C + (size_t)gr * DIMN;
        int gc0 = col0 + tx * 8;
        if (epi == 1) {
            int pos = gr % ropeL;
            const float2* rt = g_rope + pos * 112;
            #pragma unroll
            for (int j = 0; j < 8; j += 2) {
                int gc = gc0 + j;
                int d  = gc % 112;          // gc even -> d even, d <= 110
                float v0 = acc[i][j]     + bias[gc];
                float v1 = acc[i][j + 1] + bias[gc + 1];
                float2 c0 = rt[d], c1 = rt[d + 1];
                crow[gc]     = v0 * c0.x - v1 * c0.y;
                crow[gc + 1] = v1 * c1.x + v0 * c1.y;
            }
        } else {
            #pragma unroll
            for (int j = 0; j < 8; j++) {
                int gc = gc0 + j;
                float v = acc[i][j] + bias[gc];
                if (epi == 2) v += res[(size_t)gr * DIMN + gc];
                if (epi == 3) v = fmaxf(v, 0.0f);
                crow[gc] = v;
            }
        }
    }
}

// ---------------- attention: one block per (b, h) --------------------------
__global__ __launch_bounds__(256) void attn_k(const float* __restrict__ gate,
                                              float* __restrict__ out)
{
    const int b = blockIdx.x >> 3, h = blockIdx.x & 7;
    __shared__ float q_s[8][112];
    __shared__ float w_s[8][592];
    __shared__ const float* kp[NKEYS];
    __shared__ const float* vp[NKEYS];
    const int tid = threadIdx.x;

    for (int i = tid; i < 8 * 112; i += 256) {
        int r = i / 112, d = i % 112;
        q_s[r][d] = g_Q[((size_t)(b * 8 + r)) * 896 + h * 112 + d];
    }
    for (int k = tid; k < NKEYS; k += 256) {
        size_t o;
        const float *kb, *vb;
        if (k < 8)        { o = ((size_t)(b * 8 + k)) * 896 + h * 112;          kb = g_Ks + o; vb = g_Vs + o; }
        else if (k < 73)  { o = ((size_t)(b * 65 + (k - 8))) * 896 + h * 112;   kb = g_Ka + o; vb = g_Va + o; }
        else              { o = ((size_t)(b * 512 + (k - 73))) * 896 + h * 112; kb = g_Kt + o; vb = g_Vt + o; }
        kp[k] = kb; vp[k] = vb;
    }
    __syncthreads();

    const float ratio = tanhf(gate[0]);
    const float sc0   = rsqrtf(112.0f);

    // scores
    for (int k = tid; k < NKEYS; k += 256) {
        const float* kb = kp[k];
        float acc[8] = {0.f, 0.f, 0.f, 0.f, 0.f, 0.f, 0.f, 0.f};
        #pragma unroll 4
        for (int d4 = 0; d4 < 28; ++d4) {
            float4 kv = *(const float4*)(kb + d4 * 4);
            #pragma unroll
            for (int r = 0; r < 8; r++) {
                acc[r] = fmaf(q_s[r][d4 * 4 + 0], kv.x, acc[r]);
                acc[r] = fmaf(q_s[r][d4 * 4 + 1], kv.y, acc[r]);
                acc[r] = fmaf(q_s[r][d4 * 4 + 2], kv.z, acc[r]);
                acc[r] = fmaf(q_s[r][d4 * 4 + 3], kv.w, acc[r]);
            }
        }
        float sc = (k < 73) ? sc0 : sc0 * ratio;
        #pragma unroll
        for (int r = 0; r < 8; r++) w_s[r][k] = acc[r] * sc;
    }
    __syncthreads();

    // softmax: one warp per query row
    {
        int r = tid >> 5, lane = tid & 31;
        float m = -3.0e38f;
        for (int k = lane; k < NKEYS; k += 32) m = fmaxf(m, w_s[r][k]);
        #pragma unroll
        for (int o = 16; o; o >>= 1) m = fmaxf(m, __shfl_xor_sync(0xffffffffu, m, o));
        float s = 0.0f;
        for (int k = lane; k < NKEYS; k += 32) { float e = __expf(w_s[r][k] - m); w_s[r][k] = e; s += e; }
        #pragma unroll
        for (int o = 16; o; o >>= 1) s += __shfl_xor_sync(0xffffffffu, s, o);
        float inv = 1.0f / s;
        for (int k = lane; k < NKEYS; k += 32) w_s[r][k] *= inv;
    }
    __syncthreads();

    // AV
    for (int idx = tid; idx < 896; idx += 256) {
        int r = idx / 112, d = idx % 112;
        float acc = 0.0f;
        #pragma unroll 4
        for (int k = 0; k < NKEYS; k++) acc = fmaf(w_s[r][k], vp[k][d], acc);
        out[((size_t)(b * 8 + r)) * 896 + h * 112 + d] = acc;
    }
}

// ---------------- layernorm over g_y -> g_yn --------------------------------
__global__ __launch_bounds__(256) void ln_k(const float* __restrict__ g,
                                            const float* __restrict__ bt)
{
    int row = blockIdx.x;
    const float* y = g_y  + (size_t)row * 896;
    float*      yn = g_yn + (size_t)row * 896;
    int tid = threadIdx.x;
    float s = 0.0f, s2 = 0.0f;
    for (int j = tid; j < 896; j += 256) { float v = y[j]; s += v; s2 += v * v; }
    __shared__ float rs[8], rs2[8];
    #pragma unroll
    for (int o = 16; o; o >>= 1) { s += __shfl_xor_sync(~0u, s, o); s2 += __shfl_xor_sync(~0u, s2, o); }
    if ((tid & 31) == 0) { rs[tid >> 5] = s; rs2[tid >> 5] = s2; }
    __syncthreads();
    if (tid < 32) {
        s  = (tid < 8) ? rs[tid]  : 0.0f;
        s2 = (tid < 8) ? rs2[tid] : 0.0f;
        #pragma unroll
        for (int o = 4; o; o >>= 1) { s += __shfl_xor_sync(~0u, s, o); s2 += __shfl_xor_sync(~0u, s2, o); }
        if (tid == 0) { rs[0] = s; rs2[0] = s2; }
    }
    __syncthreads();
    float mu  = rs[0]  * (1.0f / 896.0f);
    float var = rs2[0] * (1.0f / 896.0f) - mu * mu;
    float inv = rsqrtf(var + 1e-5f);
    for (int j = tid; j < 896; j += 256) yn[j] = (y[j] - mu) * inv * g[j] + bt[j];
}

// ---------------- host orchestration ---------------------------------------
extern "C" void kernel_launch(void* const* d_in, const int* in_sizes, int n_in,
                              void* d_out, int out_size)
{
    const float* x   = (const float*)d_in[0];
    const float* h_a = (const float*)d_in[1];
    const float* h_t = (const float*)d_in[2];
    const float* p   = (const float*)d_in[3];
    const float* Wq  = (const float*)d_in[4],  *bq  = (const float*)d_in[5];
    const float* Wks = (const float*)d_in[6],  *bks = (const float*)d_in[7];
    const float* Wvs = (const float*)d_in[8],  *bvs = (const float*)d_in[9];
    const float* Wka = (const float*)d_in[10], *bka = (const float*)d_in[11];
    const float* Wva = (const float*)d_in[12], *bva = (const float*)d_in[13];
    const float* Wkt = (const float*)d_in[14], *bkt = (const float*)d_in[15];
    const float* Wvt = (const float*)d_in[16], *bvt = (const float*)d_in[17];
    const float* Wo  = (const float*)d_in[18], *bo  = (const float*)d_in[19];
    const float* Wf  = (const float*)d_in[20], *bf  = (const float*)d_in[21];
    const float* gate = (const float*)d_in[22];
    const float* ln_g = (const float*)d_in[23];
    const float* ln_b = (const float*)d_in[24];

    float *Q, *Ks, *Vs, *Had, *Ka, *Va, *Kt, *Vt, *attn, *y, *yn;
    cudaGetSymbolAddress((void**)&Q,    g_Q);
    cudaGetSymbolAddress((void**)&Ks,   g_Ks);
    cudaGetSymbolAddress((void**)&Vs,   g_Vs);
    cudaGetSymbolAddress((void**)&Had,  g_Had);
    cudaGetSymbolAddress((void**)&Ka,   g_Ka);
    cudaGetSymbolAddress((void**)&Va,   g_Va);
    cudaGetSymbolAddress((void**)&Kt,   g_Kt);
    cudaGetSymbolAddress((void**)&Vt,   g_Vt);
    cudaGetSymbolAddress((void**)&attn, g_attn);
    cudaGetSymbolAddress((void**)&y,    g_y);
    cudaGetSymbolAddress((void**)&yn,   g_yn);

    rope_init_k<<<(512 * 112 + 255) / 256, 256>>>();
    build_had_k<<<(4160 * 224 + 255) / 256, 256>>>(h_a, p);

    dim3 gsm(7, 4);     // M = 512
    dim3 gka(7, 33);    // M = 4160
    dim3 gkt(7, 256);   // M = 32768

    sgemm_k<<<gsm, 256>>>(x,   Wq,  bq,  Q,  512,   1, 8,   nullptr);
    sgemm_k<<<gsm, 256>>>(x,   Wks, bks, Ks, 512,   1, 8,   nullptr);
    sgemm_k<<<gsm, 256>>>(x,   Wvs, bvs, Vs, 512,   0, 0,   nullptr);
    sgemm_k<<<gka, 256>>>(Had, Wka, bka, Ka, 4160,  1, 65,  nullptr);
    sgemm_k<<<gka, 256>>>(Had, Wva, bva, Va, 4160,  0, 0,   nullptr);
    sgemm_k<<<gkt, 256>>>(h_t, Wkt, bkt, Kt, 32768, 1, 512, nullptr);
    sgemm_k<<<gkt, 256>>>(h_t, Wvt, bvt, Vt, 32768, 0, 0,   nullptr);

    attn_k<<<512, 256>>>(gate, attn);

    sgemm_k<<<gsm, 256>>>(attn, Wo, bo, y, 512, 2, 0, x);   // + residual x
    ln_k<<<512, 256>>>(ln_g, ln_b);
    sgemm_k<<<gsm, 256>>>(yn, Wf, bf, (float*)d_out, 512, 3, 0, nullptr);  // ReLU
}

// round 3
// speedup vs baseline: 1.8174x; 1.8174x over previous
#include <cuda_runtime.h>
#include <cuda_bf16.h>
#include <cstdint>

#define DIMN 896
#define NKEYS 585

// ==================== device scratch (no allocation) ========================
__device__ float  g_Q   [512   * 896];
__device__ float  g_Ks  [512   * 896];
__device__ float  g_Vs  [512   * 896];
__device__ float  g_Had [4160  * 896];
__device__ float  g_Ka  [4160  * 896];
__device__ float  g_Va  [4160  * 896];
__device__ float  g_Kt  [32768 * 896];
__device__ float  g_Vt  [32768 * 896];
__device__ float  g_attn[512   * 896];
__device__ float  g_y   [512   * 896];
__device__ float  g_yn  [512   * 896];
__device__ float2 g_rope[512 * 112];
__device__ __nv_bfloat16 g_Whi[9][896 * 896];   // W^T hi  [n][k]
__device__ __nv_bfloat16 g_Wlo[9][896 * 896];   // W^T lo  [n][k]

// ==================== helpers ===============================================
__device__ __forceinline__ uint32_t smem_u32(const void* p) {
    uint32_t a;
    asm("{ .reg .u64 t; cvta.to.shared.u64 t, %1; cvt.u32.u64 %0, t; }" : "=r"(a) : "l"(p));
    return a;
}
#define CP_ASYNC16(dst, src) asm volatile("cp.async.cg.shared.global [%0], [%1], 16;" :: "r"(dst), "l"(src))
#define CP_COMMIT()          asm volatile("cp.async.commit_group;" ::: "memory")
#define CP_WAIT0()           asm volatile("cp.async.wait_group 0;" ::: "memory")

#define LDSM4(r0, r1, r2, r3, addr) \
    asm volatile("ldmatrix.sync.aligned.m8n8.x4.shared.b16 {%0,%1,%2,%3}, [%4];" \
        : "=r"(r0), "=r"(r1), "=r"(r2), "=r"(r3) : "r"(addr))

#define MMA_BF16(d, a, b0, b1) \
    asm volatile("mma.sync.aligned.m16n8k16.row.col.f32.bf16.bf16.f32 " \
        "{%0,%1,%2,%3}, {%4,%5,%6,%7}, {%8,%9}, {%0,%1,%2,%3};" \
        : "+f"((d)[0]), "+f"((d)[1]), "+f"((d)[2]), "+f"((d)[3]) \
        : "r"((a)[0]), "r"((a)[1]), "r"((a)[2]), "r"((a)[3]), "r"(b0), "r"(b1))

// ==================== small prep kernels ====================================
__global__ void rope_init_k() {
    int i = blockIdx.x * blockDim.x + threadIdx.x;
    if (i >= 512 * 112) return;
    int pos = i / 112, d = i % 112, f = d % 56;
    float inv = powf(10000.0f, -((float)(2 * f) / 112.0f));
    float ang = (float)pos * inv;
    g_rope[i] = make_float2(cosf(ang), sinf(ang));
}

__global__ void build_had_k(const float* __restrict__ h_a, const float* __restrict__ p) {
    int i = blockIdx.x * blockDim.x + threadIdx.x;
    if (i >= 4160 * 224) return;
    int row = i / 224, c4 = i % 224;
    int b = row / 65, l = row % 65;
    const float4* src = (l < 64)
        ? (const float4*)(h_a + ((size_t)(b * 64 + l)) * 896)
        : (const float4*)(p   + (size_t)b * 896);
    ((float4*)(g_Had + (size_t)row * 896))[c4] = src[c4];
}

struct WPtrs { const float* w[9]; };
// transpose + bf16 hi/lo split of all 9 weights: W[k][n] -> Whi/Wlo[n][k]
__global__ void convw_k(WPtrs wp) {
    __shared__ float tile[32][33];
    int wi = blockIdx.z;
    const float* W = wp.w[wi];
    __nv_bfloat16* hi = g_Whi[wi];
    __nv_bfloat16* lo = g_Wlo[wi];
    int tx = threadIdx.x, ty = threadIdx.y;
    int k0 = blockIdx.y * 32, n0 = blockIdx.x * 32;
    #pragma unroll
    for (int i = 0; i < 4; i++)
        tile[ty + i * 8][tx] = W[(size_t)(k0 + ty + i * 8) * 896 + n0 + tx];
    __syncthreads();
    #pragma unroll
    for (int i = 0; i < 4; i++) {
        int n = n0 + ty + i * 8, k = k0 + tx;
        float v = tile[tx][ty + i * 8];
        __nv_bfloat16 h = __float2bfloat16_rn(v);
        float r = v - __bfloat162float(h);
        hi[(size_t)n * 896 + k] = h;
        lo[(size_t)n * 896 + k] = __float2bfloat16_rn(r);
    }
}

// ==================== warp-mma bf16-split GEMM ==============================
// C[M,896] = A[M,896](fp32) @ W[896,896]  as  Ahi*Bhi + Ahi*Blo + Alo*Bhi
// CTA tile 128x128x32, 8 warps (4Mx2N), warp tile 32x64, 2-stage pipeline.
// SMEM stage layout (bytes): Ahi 0, Alo 10240, Bhi 20480, Blo 30720; stage=40960
#define LDAB 80          // row stride in bytes (40 bf16)
#define STAGE_B 40960
#define SM_TOTAL (2 * STAGE_B)

__device__ __forceinline__ void stage_load(
    uint32_t sb, int buf, const float* __restrict__ A,
    const __nv_bfloat16* __restrict__ Bhi, const __nv_bfloat16* __restrict__ Blo,
    int M, int row0, int col0, int kt, int tid)
{
    uint32_t s0 = sb + buf * STAGE_B;
    // A: 128 rows x 32 k fp32 -> hi/lo bf16
    #pragma unroll
    for (int i = 0; i < 4; i++) {
        int c = i * 256 + tid;
        int r = c >> 3, ks = c & 7;            // ks: 4-float segment
        float4 v = make_float4(0.f, 0.f, 0.f, 0.f);
        if (row0 + r < M) v = *(const float4*)(A + (size_t)(row0 + r) * DIMN + kt + ks * 4);
        __nv_bfloat16 hx = __float2bfloat16_rn(v.x), hy = __float2bfloat16_rn(v.y);
        __nv_bfloat16 hz = __float2bfloat16_rn(v.z), hw = __float2bfloat16_rn(v.w);
        __nv_bfloat16 lx = __float2bfloat16_rn(v.x - __bfloat162float(hx));
        __nv_bfloat16 ly = __float2bfloat16_rn(v.y - __bfloat162float(hy));
        __nv_bfloat16 lz = __float2bfloat16_rn(v.z - __bfloat162float(hz));
        __nv_bfloat16 lw = __float2bfloat16_rn(v.w - __bfloat162float(hw));
        uint2 hp = make_uint2(((uint32_t)__bfloat16_as_ushort(hy) << 16) | __bfloat16_as_ushort(hx),
                              ((uint32_t)__bfloat16_as_ushort(hw) << 16) | __bfloat16_as_ushort(hz));
        uint2 lp = make_uint2(((uint32_t)__bfloat16_as_ushort(ly) << 16) | __bfloat16_as_ushort(lx),
                              ((uint32_t)__bfloat16_as_ushort(lw) << 16) | __bfloat16_as_ushort(lz));
        uint32_t off = (uint32_t)(r * LDAB + ks * 8);
        *(uint2*)(uintptr_t)0; // no-op placeholder removed by compiler? (not used)
        asm volatile("st.shared.v2.b32 [%0], {%1, %2};" :: "r"(s0 + off),         "r"(hp.x), "r"(hp.y));
        asm volatile("st.shared.v2.b32 [%0], {%1, %2};" :: "r"(s0 + 10240 + off), "r"(lp.x), "r"(lp.y));
    }
    // B: 128 n-rows x 32 k bf16, hi+lo, via cp.async (16B chunks)
    #pragma unroll
    for (int i = 0; i < 4; i++) {
        int c = i * 256 + tid;
        int var = c >> 9, r = (c >> 2) & 127, ks = c & 3;
        const __nv_bfloat16* src = (var ? Blo : Bhi) + (size_t)(col0 + r) * DIMN + kt + ks * 8;
        uint32_t dst = s0 + 20480 + var * 10240 + (uint32_t)(r * LDAB + ks * 16);
        CP_ASYNC16(dst, src);
    }
}

// epi: 0 +bias; 1 +bias,RoPE(ropeL); 2 +bias+res; 3 +bias,ReLU
__global__ __launch_bounds__(256, 1) void wgemm_k(
    const float* __restrict__ A, const __nv_bfloat16* __restrict__ Bhi,
    const __nv_bfloat16* __restrict__ Blo, const float* __restrict__ bias,
    float* __restrict__ C, int M, int epi, int ropeL, const float* __restrict__ res)
{
    extern __shared__ __align__(128) char smx[];
    const int tid  = threadIdx.x;
    const int lane = tid & 31, wid = tid >> 5;
    const int wm = (wid & 3) * 32, wn = (wid >> 2) * 64;
    const int row0 = blockIdx.y * 128, col0 = blockIdx.x * 128;
    uint32_t sb = smem_u32(smx);

    float acc[2][8][4];
    #pragma unroll
    for (int mi = 0; mi < 2; mi++)
        #pragma unroll
        for (int nj = 0; nj < 8; nj++)
            #pragma unroll
            for (int q = 0; q < 4; q++) acc[mi][nj][q] = 0.0f;

    // lane-derived ldmatrix address components
    const int a_r = lane & 15;
    const int a_k = (lane >> 4) * 16;                       // bytes
    const int b_r = (lane & 7) + ((lane >> 4) & 1) * 8;
    const int b_k = ((lane >> 3) & 1) * 16;                 // bytes

    stage_load(sb, 0, A, Bhi, Blo, M, row0, col0, 0, tid);
    CP_COMMIT();

    #pragma unroll 1
    for (int t = 0; t < 28; t++) {
        const int buf = t & 1;
        CP_WAIT0();
        __syncthreads();
        if (t + 1 < 28) {
            stage_load(sb, buf ^ 1, A, Bhi, Blo, M, row0, col0, (t + 1) * 32, tid);
            CP_COMMIT();
        }
        uint32_t s0 = sb + buf * STAGE_B;
        uint32_t aHiB = s0 +         (uint32_t)((wm + a_r) * LDAB + a_k);
        uint32_t aLoB = aHiB + 10240;
        uint32_t bHiB = s0 + 20480 + (uint32_t)((wn + b_r) * LDAB + b_k);
        uint32_t bLoB = bHiB + 10240;
        #pragma unroll
        for (int ks = 0; ks < 2; ks++) {
            const uint32_t ksb = ks * 32;
            uint32_t ah[2][4], al[2][4], bh[8][2], bl[8][2];
            #pragma unroll
            for (int mi = 0; mi < 2; mi++) {
                LDSM4(ah[mi][0], ah[mi][1], ah[mi][2], ah[mi][3], aHiB + mi * (16 * LDAB) + ksb);
                LDSM4(al[mi][0], al[mi][1], al[mi][2], al[mi][3], aLoB + mi * (16 * LDAB) + ksb);
            }
            #pragma unroll
            for (int p = 0; p < 4; p++) {
                LDSM4(bh[2*p][0], bh[2*p][1], bh[2*p+1][0], bh[2*p+1][1], bHiB + p * (16 * LDAB) + ksb);
                LDSM4(bl[2*p][0], bl[2*p][1], bl[2*p+1][0], bl[2*p+1][1], bLoB + p * (16 * LDAB) + ksb);
            }
            #pragma unroll
            for (int mi = 0; mi < 2; mi++)
                #pragma unroll
                for (int nj = 0; nj < 8; nj++)
                    MMA_BF16(acc[mi][nj], ah[mi], bh[nj][0], bh[nj][1]);
            #pragma unroll
            for (int mi = 0; mi < 2; mi++)
                #pragma unroll
                for (int nj = 0; nj < 8; nj++)
                    MMA_BF16(acc[mi][nj], ah[mi], bl[nj][0], bl[nj][1]);
            #pragma unroll
            for (int mi = 0; mi < 2; mi++)
                #pragma unroll
                for (int nj = 0; nj < 8; nj++)
                    MMA_BF16(acc[mi][nj], al[mi], bh[nj][0], bh[nj][1]);
        }
    }

    // ---------------- epilogue ----------------
    #pragma unroll
    for (int mi = 0; mi < 2; mi++) {
        #pragma unroll
        for (int half = 0; half < 2; half++) {
            int row = row0 + wm + mi * 16 + (lane >> 2) + half * 8;
            if (row >= M) continue;
            float* crow = C + (size_t)row * DIMN;
            const float2* rt = (epi == 1) ? (g_rope + (size_t)(row % ropeL) * 112) : nullptr;
            const float* rrow = (epi == 2) ? (res + (size_t)row * DIMN) : nullptr;
            #pragma unroll
            for (int nj = 0; nj < 8; nj++) {
                int gc = col0 + wn + nj * 8 + (lane & 3) * 2;
                float v0 = acc[mi][nj][half * 2]     + bias[gc];
                float v1 = acc[mi][nj][half * 2 + 1] + bias[gc + 1];
                float2 o;
                if (epi == 1) {
                    int d = gc % 112;
                    float2 r0 = rt[d], r1 = rt[d + 1];
                    o.x = v0 * r0.x - v1 * r0.y;
                    o.y = v1 * r1.x + v0 * r1.y;
                } else if (epi == 2) {
                    o.x = v0 + rrow[gc]; o.y = v1 + rrow[gc + 1];
                } else if (epi == 3) {
                    o.x = fmaxf(v0, 0.f); o.y = fmaxf(v1, 0.f);
                } else {
                    o.x = v0; o.y = v1;
                }
                *(float2*)(crow + gc) = o;
            }
        }
    }
}

// ==================== attention =============================================
__global__ __launch_bounds__(256) void attn_k(const float* __restrict__ gate,
                                              float* __restrict__ out)
{
    const int b = blockIdx.x >> 3, h = blockIdx.x & 7;
    __shared__ float q_s[8][112];
    __shared__ float w_s[8][592];
    __shared__ const float* kp[NKEYS];
    __shared__ const float* vp[NKEYS];
    const int tid = threadIdx.x;

    for (int i = tid; i < 8 * 112; i += 256) {
        int r = i / 112, d = i % 112;
        q_s[r][d] = g_Q[((size_t)(b * 8 + r)) * 896 + h * 112 + d];
    }
    for (int k = tid; k < NKEYS; k += 256) {
        size_t o;
        const float *kb, *vb;
        if (k < 8)       { o = ((size_t)(b * 8 + k)) * 896 + h * 112;          kb = g_Ks + o; vb = g_Vs + o; }
        else if (k < 73) { o = ((size_t)(b * 65 + (k - 8))) * 896 + h * 112;   kb = g_Ka + o; vb = g_Va + o; }
        else             { o = ((size_t)(b * 512 + (k - 73))) * 896 + h * 112; kb = g_Kt + o; vb = g_Vt + o; }
        kp[k] = kb; vp[k] = vb;
    }
    __syncthreads();

    const float ratio = tanhf(gate[0]);
    const float sc0   = rsqrtf(112.0f);

    for (int k = tid; k < NKEYS; k += 256) {
        const float* kb = kp[k];
        float acc[8] = {0.f, 0.f, 0.f, 0.f, 0.f, 0.f, 0.f, 0.f};
        #pragma unroll 4
        for (int d4 = 0; d4 < 28; ++d4) {
            float4 kv = *(const float4*)(kb + d4 * 4);
            #pragma unroll
            for (int r = 0; r < 8; r++) {
                acc[r] = fmaf(q_s[r][d4 * 4 + 0], kv.x, acc[r]);
                acc[r] = fmaf(q_s[r][d4 * 4 + 1], kv.y, acc[r]);
                acc[r] = fmaf(q_s[r][d4 * 4 + 2], kv.z, acc[r]);
                acc[r] = fmaf(q_s[r][d4 * 4 + 3], kv.w, acc[r]);
            }
        }
        float sc = (k < 73) ? sc0 : sc0 * ratio;
        #pragma unroll
        for (int r = 0; r < 8; r++) w_s[r][k] = acc[r] * sc;
    }
    __syncthreads();

    {
        int r = tid >> 5, lane = tid & 31;
        float m = -3.0e38f;
        for (int k = lane; k < NKEYS; k += 32) m = fmaxf(m, w_s[r][k]);
        #pragma unroll
        for (int o = 16; o; o >>= 1) m = fmaxf(m, __shfl_xor_sync(0xffffffffu, m, o));
        float s = 0.0f;
        for (int k = lane; k < NKEYS; k += 32) { float e = __expf(w_s[r][k] - m); w_s[r][k] = e; s += e; }
        #pragma unroll
        for (int o = 16; o; o >>= 1) s += __shfl_xor_sync(0xffffffffu, s, o);
        float inv = 1.0f / s;
        for (int k = lane; k < NKEYS; k += 32) w_s[r][k] *= inv;
    }
    __syncthreads();

    for (int idx = tid; idx < 896; idx += 256) {
        int r = idx / 112, d = idx % 112;
        float acc = 0.0f;
        #pragma unroll 4
        for (int k = 0; k < NKEYS; k++) acc = fmaf(w_s[r][k], vp[k][d], acc);
        out[((size_t)(b * 8 + r)) * 896 + h * 112 + d] = acc;
    }
}

// ==================== layernorm =============================================
__global__ __launch_bounds__(256) void ln_k(const float* __restrict__ g,
                                            const float* __restrict__ bt)
{
    int row = blockIdx.x;
    const float* y = g_y  + (size_t)row * 896;
    float*      yn = g_yn + (size_t)row * 896;
    int tid = threadIdx.x;
    float s = 0.0f, s2 = 0.0f;
    for (int j = tid; j < 896; j += 256) { float v = y[j]; s += v; s2 += v * v; }
    __shared__ float rs[8], rs2[8];
    #pragma unroll
    for (int o = 16; o; o >>= 1) { s += __shfl_xor_sync(~0u, s, o); s2 += __shfl_xor_sync(~0u, s2, o); }
    if ((tid & 31) == 0) { rs[tid >> 5] = s; rs2[tid >> 5] = s2; }
    __syncthreads();
    if (tid < 32) {
        s  = (tid < 8) ? rs[tid]  : 0.0f;
        s2 = (tid < 8) ? rs2[tid] : 0.0f;
        #pragma unroll
        for (int o = 4; o; o >>= 1) { s += __shfl_xor_sync(~0u, s, o); s2 += __shfl_xor_sync(~0u, s2, o); }
        if (tid == 0) { rs[0] = s; rs2[0] = s2; }
    }
    __syncthreads();
    float mu  = rs[0]  * (1.0f / 896.0f);
    float var = rs2[0] * (1.0f / 896.0f) - mu * mu;
    float inv = rsqrtf(var + 1e-5f);
    for (int j = tid; j < 896; j += 256) yn[j] = (y[j] - mu) * inv * g[j] + bt[j];
}

// ==================== host orchestration ====================================
extern "C" void kernel_launch(void* const* d_in, const int* in_sizes, int n_in,
                              void* d_out, int out_size)
{
    const float* x   = (const float*)d_in[0];
    const float* h_a = (const float*)d_in[1];
    const float* h_t = (const float*)d_in[2];
    const float* p   = (const float*)d_in[3];
    const float* Wq  = (const float*)d_in[4],  *bq  = (const float*)d_in[5];
    const float* Wks = (const float*)d_in[6],  *bks = (const float*)d_in[7];
    const float* Wvs = (const float*)d_in[8],  *bvs = (const float*)d_in[9];
    const float* Wka = (const float*)d_in[10], *bka = (const float*)d_in[11];
    const float* Wva = (const float*)d_in[12], *bva = (const float*)d_in[13];
    const float* Wkt = (const float*)d_in[14], *bkt = (const float*)d_in[15];
    const float* Wvt = (const float*)d_in[16], *bvt = (const float*)d_in[17];
    const float* Wo  = (const float*)d_in[18], *bo  = (const float*)d_in[19];
    const float* Wf  = (const float*)d_in[20], *bf  = (const float*)d_in[21];
    const float* gate = (const float*)d_in[22];
    const float* ln_g = (const float*)d_in[23];
    const float* ln_b = (const float*)d_in[24];

    float *Q, *Ks, *Vs, *Had, *Ka, *Va, *Kt, *Vt, *attn, *y, *yn;
    __nv_bfloat16 *Whi, *Wlo;
    cudaGetSymbolAddress((void**)&Q,    g_Q);
    cudaGetSymbolAddress((void**)&Ks,   g_Ks);
    cudaGetSymbolAddress((void**)&Vs,   g_Vs);
    cudaGetSymbolAddress((void**)&Had,  g_Had);
    cudaGetSymbolAddress((void**)&Ka,   g_Ka);
    cudaGetSymbolAddress((void**)&Va,   g_Va);
    cudaGetSymbolAddress((void**)&Kt,   g_Kt);
    cudaGetSymbolAddress((void**)&Vt,   g_Vt);
    cudaGetSymbolAddress((void**)&attn, g_attn);
    cudaGetSymbolAddress((void**)&y,    g_y);
    cudaGetSymbolAddress((void**)&yn,   g_yn);
    cudaGetSymbolAddress((void**)&Whi,  g_Whi);
    cudaGetSymbolAddress((void**)&Wlo,  g_Wlo);

    cudaFuncSetAttribute(wgemm_k, cudaFuncAttributeMaxDynamicSharedMemorySize, SM_TOTAL);

    rope_init_k<<<(512 * 112 + 255) / 256, 256>>>();
    build_had_k<<<(4160 * 224 + 255) / 256, 256>>>(h_a, p);

    WPtrs wp;
    wp.w[0] = Wq; wp.w[1] = Wks; wp.w[2] = Wvs; wp.w[3] = Wka; wp.w[4] = Wva;
    wp.w[5] = Wkt; wp.w[6] = Wvt; wp.w[7] = Wo; wp.w[8] = Wf;
    convw_k<<<dim3(28, 28, 9), dim3(32, 8)>>>(wp);

    const size_t WS = 896 * 896;
    dim3 gsm(7, 4);     // M = 512
    dim3 gka(7, 33);    // M = 4160
    dim3 gkt(7, 256);   // M = 32768

    wgemm_k<<<gsm, 256, SM_TOTAL>>>(x,   Whi + 0 * WS, Wlo + 0 * WS, bq,  Q,  512,   1, 8,   nullptr);
    wgemm_k<<<gsm, 256, SM_TOTAL>>>(x,   Whi + 1 * WS, Wlo + 1 * WS, bks, Ks, 512,   1, 8,   nullptr);
    wgemm_k<<<gsm, 256, SM_TOTAL>>>(x,   Whi + 2 * WS, Wlo + 2 * WS, bvs, Vs, 512,   0, 0,   nullptr);
    wgemm_k<<<gka, 256, SM_TOTAL>>>(Had, Whi + 3 * WS, Wlo + 3 * WS, bka, Ka, 4160,  1, 65,  nullptr);
    wgemm_k<<<gka, 256, SM_TOTAL>>>(Had, Whi + 4 * WS, Wlo + 4 * WS, bva, Va, 4160,  0, 0,   nullptr);
    wgemm_k<<<gkt, 256, SM_TOTAL>>>(h_t, Whi + 5 * WS, Wlo + 5 * WS, bkt, Kt, 32768, 1, 512, nullptr);
    wgemm_k<<<gkt, 256, SM_TOTAL>>>(h_t, Whi + 6 * WS, Wlo + 6 * WS, bvt, Vt, 32768, 0, 0,   nullptr);

    attn_k<<<512, 256>>>(gate, attn);

    wgemm_k<<<gsm, 256, SM_TOTAL>>>(attn, Whi + 7 * WS, Wlo + 7 * WS, bo, y, 512, 2, 0, x);
    ln_k<<<512, 256>>>(ln_g, ln_b);
    wgemm_k<<<gsm, 256, SM_TOTAL>>>(yn, Whi + 8 * WS, Wlo + 8 * WS, bf, (float*)d_out, 512, 3, 0, nullptr);
}

// round 4
// speedup vs baseline: 2.1613x; 1.1893x over previous
#include <cuda_runtime.h>
#include <cuda_bf16.h>
#include <cstdint>

#define DIMN 896
#define NKEYS 585

// ==================== device scratch (no allocation) ========================
__device__ float  g_Q   [512   * 896];
__device__ float  g_Ks  [512   * 896];
__device__ float  g_Vs  [512   * 896];
__device__ float  g_Ka  [4160  * 896];
__device__ float  g_Va  [4160  * 896];
__device__ float  g_Kt  [32768 * 896];
__device__ float  g_Vt  [32768 * 896];
__device__ float  g_y   [512   * 896];
__device__ float2 g_rope[512 * 112];
__device__ __nv_bfloat16 g_Whi[9][896 * 896];   // W^T hi  [n][k]
__device__ __nv_bfloat16 g_Wlo[9][896 * 896];   // W^T lo  [n][k]
// pre-split activations (hi/lo bf16)
__device__ __nv_bfloat16 g_xh   [512   * 896], g_xl   [512   * 896];
__device__ __nv_bfloat16 g_hadh [4224  * 896], g_hadl [4224  * 896];
__device__ __nv_bfloat16 g_hth  [32768 * 896], g_htl  [32768 * 896];
__device__ __nv_bfloat16 g_ath  [512   * 896], g_atl  [512   * 896];
__device__ __nv_bfloat16 g_ynh  [512   * 896], g_ynl  [512   * 896];

// ==================== helpers ===============================================
__device__ __forceinline__ uint32_t smem_u32(const void* p) {
    uint32_t a;
    asm("{ .reg .u64 t; cvta.to.shared.u64 t, %1; cvt.u32.u64 %0, t; }" : "=r"(a) : "l"(p));
    return a;
}
#define CP_ASYNC16(dst, src) asm volatile("cp.async.cg.shared.global [%0], [%1], 16;" :: "r"(dst), "l"(src))
#define CP_COMMIT()          asm volatile("cp.async.commit_group;" ::: "memory")
#define CP_WAIT1()           asm volatile("cp.async.wait_group 1;" ::: "memory")

#define LDSM4(r0, r1, r2, r3, addr) \
    asm volatile("ldmatrix.sync.aligned.m8n8.x4.shared.b16 {%0,%1,%2,%3}, [%4];" \
        : "=r"(r0), "=r"(r1), "=r"(r2), "=r"(r3) : "r"(addr))

#define MMA_BF16(d, a, b0, b1) \
    asm volatile("mma.sync.aligned.m16n8k16.row.col.f32.bf16.bf16.f32 " \
        "{%0,%1,%2,%3}, {%4,%5,%6,%7}, {%8,%9}, {%0,%1,%2,%3};" \
        : "+f"((d)[0]), "+f"((d)[1]), "+f"((d)[2]), "+f"((d)[3]) \
        : "r"((a)[0]), "r"((a)[1]), "r"((a)[2]), "r"((a)[3]), "r"(b0), "r"(b1))

__device__ __forceinline__ void split4(float4 v, uint2& hp, uint2& lp) {
    __nv_bfloat16 hx = __float2bfloat16_rn(v.x), hy = __float2bfloat16_rn(v.y);
    __nv_bfloat16 hz = __float2bfloat16_rn(v.z), hw = __float2bfloat16_rn(v.w);
    __nv_bfloat16 lx = __float2bfloat16_rn(v.x - __bfloat162float(hx));
    __nv_bfloat16 ly = __float2bfloat16_rn(v.y - __bfloat162float(hy));
    __nv_bfloat16 lz = __float2bfloat16_rn(v.z - __bfloat162float(hz));
    __nv_bfloat16 lw = __float2bfloat16_rn(v.w - __bfloat162float(hw));
    hp = make_uint2(((uint32_t)__bfloat16_as_ushort(hy) << 16) | __bfloat16_as_ushort(hx),
                    ((uint32_t)__bfloat16_as_ushort(hw) << 16) | __bfloat16_as_ushort(hz));
    lp = make_uint2(((uint32_t)__bfloat16_as_ushort(ly) << 16) | __bfloat16_as_ushort(lx),
                    ((uint32_t)__bfloat16_as_ushort(lw) << 16) | __bfloat16_as_ushort(lz));
}

// ==================== small prep kernels ====================================
__global__ void rope_init_k() {
    int i = blockIdx.x * blockDim.x + threadIdx.x;
    if (i >= 512 * 112) return;
    int pos = i / 112, d = i % 112, f = d % 56;
    float inv = powf(10000.0f, -((float)(2 * f) / 112.0f));
    float ang = (float)pos * inv;
    g_rope[i] = make_float2(cosf(ang), sinf(ang));
}

__global__ void split_k(const float* __restrict__ src, __nv_bfloat16* __restrict__ hi,
                        __nv_bfloat16* __restrict__ lo, int n4)
{
    int i = blockIdx.x * blockDim.x + threadIdx.x;
    if (i >= n4) return;
    float4 v = ((const float4*)src)[i];
    uint2 hp, lp;
    split4(v, hp, lp);
    ((uint2*)hi)[i] = hp;
    ((uint2*)lo)[i] = lp;
}

// build h_ad = concat(h_a, p) -> hi/lo bf16, padded to 4224 rows (zeros)
__global__ void build_had_k(const float* __restrict__ h_a, const float* __restrict__ p) {
    int i = blockIdx.x * blockDim.x + threadIdx.x;
    if (i >= 4224 * 224) return;
    int row = i / 224, c4 = i % 224;
    float4 v = make_float4(0.f, 0.f, 0.f, 0.f);
    if (row < 4160) {
        int b = row / 65, l = row % 65;
        v = (l < 64) ? ((const float4*)(h_a + ((size_t)(b * 64 + l)) * 896))[c4]
                     : ((const float4*)(p   + (size_t)b * 896))[c4];
    }
    uint2 hp, lp;
    split4(v, hp, lp);
    ((uint2*)g_hadh)[i] = hp;
    ((uint2*)g_hadl)[i] = lp;
}

struct WPtrs { const float* w[9]; };
// transpose + bf16 hi/lo split of all 9 weights: W[k][n] -> Whi/Wlo[n][k]
__global__ void convw_k(WPtrs wp) {
    __shared__ float tile[32][33];
    int wi = blockIdx.z;
    const float* W = wp.w[wi];
    __nv_bfloat16* hi = g_Whi[wi];
    __nv_bfloat16* lo = g_Wlo[wi];
    int tx = threadIdx.x, ty = threadIdx.y;
    int k0 = blockIdx.y * 32, n0 = blockIdx.x * 32;
    #pragma unroll
    for (int i = 0; i < 4; i++)
        tile[ty + i * 8][tx] = W[(size_t)(k0 + ty + i * 8) * 896 + n0 + tx];
    __syncthreads();
    #pragma unroll
    for (int i = 0; i < 4; i++) {
        int n = n0 + ty + i * 8, k = k0 + tx;
        float v = tile[tx][ty + i * 8];
        __nv_bfloat16 h = __float2bfloat16_rn(v);
        float r = v - __bfloat162float(h);
        hi[(size_t)n * 896 + k] = h;
        lo[(size_t)n * 896 + k] = __float2bfloat16_rn(r);
    }
}

// ==================== warp-mma bf16-split GEMM ==============================
// C[M, NW*896] = A @ concat(W_i); A pre-split hi/lo bf16; 3-pass split MMA.
// CTA tile 128x128x32, 8 warps (4Mx2N), 3-stage cp.async pipeline.
// stage layout (bytes): Ahi 0, Alo 10240, Bhi 20480, Blo 30720; stage=40960
#define LDAB 80
#define STAGE_B 40960
#define SM_TOTAL (3 * STAGE_B)

struct OutD {
    float* out[3];
    const float* bias[3];
    int epi[3];     // 0 bias; 1 bias+RoPE; 2 bias+res; 3 bias+ReLU
    int rl[3];
    const float* res;
};

__device__ __forceinline__ void stage_load(
    uint32_t s0, const __nv_bfloat16* __restrict__ Ahi, const __nv_bfloat16* __restrict__ Alo,
    const __nv_bfloat16* __restrict__ Bhi, const __nv_bfloat16* __restrict__ Blo,
    int row0, int col0, int kt, int tid)
{
    #pragma unroll
    for (int i = 0; i < 8; i++) {
        const int sel = i >> 1;
        int cc = (i & 1) * 256 + tid;
        int r = cc >> 2, ks = cc & 3;
        const __nv_bfloat16* base = (sel == 0) ? Ahi : (sel == 1) ? Alo : (sel == 2) ? Bhi : Blo;
        int rowg = (sel < 2) ? (row0 + r) : (col0 + r);
        uint32_t dst = s0 + (uint32_t)sel * 10240u + (uint32_t)(r * LDAB + ks * 16);
        CP_ASYNC16(dst, base + (size_t)rowg * 896 + kt + ks * 8);
    }
}

__global__ __launch_bounds__(256, 1) void wgemm_k(
    const __nv_bfloat16* __restrict__ Ahi, const __nv_bfloat16* __restrict__ Alo,
    const __nv_bfloat16* __restrict__ Bhi, const __nv_bfloat16* __restrict__ Blo,
    OutD od, int M)
{
    extern __shared__ __align__(128) char smx[];
    const int tid  = threadIdx.x;
    const int lane = tid & 31, wid = tid >> 5;
    const int wm = (wid & 3) * 32, wn = (wid >> 2) * 64;
    const int row0 = blockIdx.y * 128;
    const int col0 = blockIdx.x * 128;       // global concatenated n
    uint32_t sb = smem_u32(smx);

    float acc[2][8][4];
    #pragma unroll
    for (int mi = 0; mi < 2; mi++)
        #pragma unroll
        for (int nj = 0; nj < 8; nj++)
            #pragma unroll
            for (int q = 0; q < 4; q++) acc[mi][nj][q] = 0.0f;

    const int a_r = lane & 15;
    const int a_k = (lane >> 4) * 16;
    const int b_r = (lane & 7) + ((lane >> 4) & 1) * 8;
    const int b_k = ((lane >> 3) & 1) * 16;

    stage_load(sb, Ahi, Alo, Bhi, Blo, row0, col0, 0, tid);
    CP_COMMIT();
    stage_load(sb + STAGE_B, Ahi, Alo, Bhi, Blo, row0, col0, 32, tid);
    CP_COMMIT();

    #pragma unroll 1
    for (int t = 0; t < 28; t++) {
        CP_WAIT1();
        __syncthreads();
        if (t + 2 < 28)
            stage_load(sb + ((t + 2) % 3) * STAGE_B, Ahi, Alo, Bhi, Blo, row0, col0, (t + 2) * 32, tid);
        CP_COMMIT();

        uint32_t s0 = sb + (t % 3) * STAGE_B;
        uint32_t aHiB = s0 +         (uint32_t)((wm + a_r) * LDAB + a_k);
        uint32_t aLoB = aHiB + 10240;
        uint32_t bHiB = s0 + 20480 + (uint32_t)((wn + b_r) * LDAB + b_k);
        uint32_t bLoB = bHiB + 10240;
        #pragma unroll
        for (int ks = 0; ks < 2; ks++) {
            const uint32_t ksb = ks * 32;
            uint32_t ah[2][4], al[2][4], bh[8][2], bl[8][2];
            #pragma unroll
            for (int mi = 0; mi < 2; mi++) {
                LDSM4(ah[mi][0], ah[mi][1], ah[mi][2], ah[mi][3], aHiB + mi * (16 * LDAB) + ksb);
                LDSM4(al[mi][0], al[mi][1], al[mi][2], al[mi][3], aLoB + mi * (16 * LDAB) + ksb);
            }
            #pragma unroll
            for (int p = 0; p < 4; p++) {
                LDSM4(bh[2*p][0], bh[2*p][1], bh[2*p+1][0], bh[2*p+1][1], bHiB + p * (16 * LDAB) + ksb);
                LDSM4(bl[2*p][0], bl[2*p][1], bl[2*p+1][0], bl[2*p+1][1], bLoB + p * (16 * LDAB) + ksb);
            }
            #pragma unroll
            for (int mi = 0; mi < 2; mi++)
                #pragma unroll
                for (int nj = 0; nj < 8; nj++)
                    MMA_BF16(acc[mi][nj], ah[mi], bh[nj][0], bh[nj][1]);
            #pragma unroll
            for (int mi = 0; mi < 2; mi++)
                #pragma unroll
                for (int nj = 0; nj < 8; nj++)
                    MMA_BF16(acc[mi][nj], ah[mi], bl[nj][0], bl[nj][1]);
            #pragma unroll
            for (int mi = 0; mi < 2; mi++)
                #pragma unroll
                for (int nj = 0; nj < 8; nj++)
                    MMA_BF16(acc[mi][nj], al[mi], bh[nj][0], bh[nj][1]);
        }
    }

    // ---------------- epilogue ----------------
    const int cb = blockIdx.x / 7;            // weight slab
    const int lcol0 = (blockIdx.x % 7) * 128; // column within slab
    float* Co = od.out[cb];
    const float* bias = od.bias[cb];
    const int epi = od.epi[cb];
    const int ropeL = od.rl[cb];

    #pragma unroll
    for (int mi = 0; mi < 2; mi++) {
        #pragma unroll
        for (int half = 0; half < 2; half++) {
            int row = row0 + wm + mi * 16 + (lane >> 2) + half * 8;
            if (row >= M) continue;
            float* crow = Co + (size_t)row * DIMN;
            const float2* rt = (epi == 1) ? (g_rope + (size_t)(row % ropeL) * 112) : nullptr;
            const float* rrow = (epi == 2) ? (od.res + (size_t)row * DIMN) : nullptr;
            #pragma unroll
            for (int nj = 0; nj < 8; nj++) {
                int gc = lcol0 + wn + nj * 8 + (lane & 3) * 2;
                float v0 = acc[mi][nj][half * 2]     + bias[gc];
                float v1 = acc[mi][nj][half * 2 + 1] + bias[gc + 1];
                float2 o;
                if (epi == 1) {
                    int d = gc % 112;
                    float2 r0 = rt[d], r1 = rt[d + 1];
                    o.x = v0 * r0.x - v1 * r0.y;
                    o.y = v1 * r1.x + v0 * r1.y;
                } else if (epi == 2) {
                    o.x = v0 + rrow[gc]; o.y = v1 + rrow[gc + 1];
                } else if (epi == 3) {
                    o.x = fmaxf(v0, 0.f); o.y = fmaxf(v1, 0.f);
                } else {
                    o.x = v0; o.y = v1;
                }
                *(float2*)(crow + gc) = o;
            }
        }
    }
}

// ==================== attention (emits hi/lo bf16) ==========================
__global__ __launch_bounds__(256) void attn_k(const float* __restrict__ gate)
{
    const int b = blockIdx.x >> 3, h = blockIdx.x & 7;
    __shared__ float q_s[8][112];
    __shared__ float w_s[8][592];
    __shared__ const float* kp[NKEYS];
    __shared__ const float* vp[NKEYS];
    const int tid = threadIdx.x;

    for (int i = tid; i < 8 * 112; i += 256) {
        int r = i / 112, d = i % 112;
        q_s[r][d] = g_Q[((size_t)(b * 8 + r)) * 896 + h * 112 + d];
    }
    for (int k = tid; k < NKEYS; k += 256) {
        size_t o;
        const float *kb, *vb;
        if (k < 8)       { o = ((size_t)(b * 8 + k)) * 896 + h * 112;          kb = g_Ks + o; vb = g_Vs + o; }
        else if (k < 73) { o = ((size_t)(b * 65 + (k - 8))) * 896 + h * 112;   kb = g_Ka + o; vb = g_Va + o; }
        else             { o = ((size_t)(b * 512 + (k - 73))) * 896 + h * 112; kb = g_Kt + o; vb = g_Vt + o; }
        kp[k] = kb; vp[k] = vb;
    }
    __syncthreads();

    const float ratio = tanhf(gate[0]);
    const float sc0   = rsqrtf(112.0f);

    for (int k = tid; k < NKEYS; k += 256) {
        const float* kb = kp[k];
        float acc[8] = {0.f, 0.f, 0.f, 0.f, 0.f, 0.f, 0.f, 0.f};
        #pragma unroll 4
        for (int d4 = 0; d4 < 28; ++d4) {
            float4 kv = *(const float4*)(kb + d4 * 4);
            #pragma unroll
            for (int r = 0; r < 8; r++) {
                acc[r] = fmaf(q_s[r][d4 * 4 + 0], kv.x, acc[r]);
                acc[r] = fmaf(q_s[r][d4 * 4 + 1], kv.y, acc[r]);
                acc[r] = fmaf(q_s[r][d4 * 4 + 2], kv.z, acc[r]);
                acc[r] = fmaf(q_s[r][d4 * 4 + 3], kv.w, acc[r]);
            }
        }
        float sc = (k < 73) ? sc0 : sc0 * ratio;
        #pragma unroll
        for (int r = 0; r < 8; r++) w_s[r][k] = acc[r] * sc;
    }
    __syncthreads();

    {
        int r = tid >> 5, lane = tid & 31;
        float m = -3.0e38f;
        for (int k = lane; k < NKEYS; k += 32) m = fmaxf(m, w_s[r][k]);
        #pragma unroll
        for (int o = 16; o; o >>= 1) m = fmaxf(m, __shfl_xor_sync(0xffffffffu, m, o));
        float s = 0.0f;
        for (int k = lane; k < NKEYS; k += 32) { float e = __expf(w_s[r][k] - m); w_s[r][k] = e; s += e; }
        #pragma unroll
        for (int o = 16; o; o >>= 1) s += __shfl_xor_sync(0xffffffffu, s, o);
        float inv = 1.0f / s;
        for (int k = lane; k < NKEYS; k += 32) w_s[r][k] *= inv;
    }
    __syncthreads();

    for (int idx = tid; idx < 896; idx += 256) {
        int r = idx / 112, d = idx % 112;
        float acc = 0.0f;
        #pragma unroll 4
        for (int k = 0; k < NKEYS; k++) acc = fmaf(w_s[r][k], vp[k][d], acc);
        size_t oidx = ((size_t)(b * 8 + r)) * 896 + h * 112 + d;
        __nv_bfloat16 hv = __float2bfloat16_rn(acc);
        g_ath[oidx] = hv;
        g_atl[oidx] = __float2bfloat16_rn(acc - __bfloat162float(hv));
    }
}

// ==================== layernorm (emits hi/lo bf16) ==========================
__global__ __launch_bounds__(256) void ln_k(const float* __restrict__ g,
                                            const float* __restrict__ bt)
{
    int row = blockIdx.x;
    const float* y = g_y + (size_t)row * 896;
    int tid = threadIdx.x;
    float s = 0.0f, s2 = 0.0f;
    for (int j = tid; j < 896; j += 256) { float v = y[j]; s += v; s2 += v * v; }
    __shared__ float rs[8], rs2[8];
    #pragma unroll
    for (int o = 16; o; o >>= 1) { s += __shfl_xor_sync(~0u, s, o); s2 += __shfl_xor_sync(~0u, s2, o); }
    if ((tid & 31) == 0) { rs[tid >> 5] = s; rs2[tid >> 5] = s2; }
    __syncthreads();
    if (tid < 32) {
        s  = (tid < 8) ? rs[tid]  : 0.0f;
        s2 = (tid < 8) ? rs2[tid] : 0.0f;
        #pragma unroll
        for (int o = 4; o; o >>= 1) { s += __shfl_xor_sync(~0u, s, o); s2 += __shfl_xor_sync(~0u, s2, o); }
        if (tid == 0) { rs[0] = s; rs2[0] = s2; }
    }
    __syncthreads();
    float mu  = rs[0]  * (1.0f / 896.0f);
    float var = rs2[0] * (1.0f / 896.0f) - mu * mu;
    float inv = rsqrtf(var + 1e-5f);
    for (int j = tid; j < 896; j += 256) {
        float v = (y[j] - mu) * inv * g[j] + bt[j];
        __nv_bfloat16 hv = __float2bfloat16_rn(v);
        g_ynh[(size_t)row * 896 + j] = hv;
        g_ynl[(size_t)row * 896 + j] = __float2bfloat16_rn(v - __bfloat162float(hv));
    }
}

// ==================== host orchestration ====================================
extern "C" void kernel_launch(void* const* d_in, const int* in_sizes, int n_in,
                              void* d_out, int out_size)
{
    const float* x   = (const float*)d_in[0];
    const float* h_a = (const float*)d_in[1];
    const float* h_t = (const float*)d_in[2];
    const float* p   = (const float*)d_in[3];
    const float* Wq  = (const float*)d_in[4],  *bq  = (const float*)d_in[5];
    const float* Wks = (const float*)d_in[6],  *bks = (const float*)d_in[7];
    const float* Wvs = (const float*)d_in[8],  *bvs = (const float*)d_in[9];
    const float* Wka = (const float*)d_in[10], *bka = (const float*)d_in[11];
    const float* Wva = (const float*)d_in[12], *bva = (const float*)d_in[13];
    const float* Wkt = (const float*)d_in[14], *bkt = (const float*)d_in[15];
    const float* Wvt = (const float*)d_in[16], *bvt = (const float*)d_in[17];
    const float* Wo  = (const float*)d_in[18], *bo  = (const float*)d_in[19];
    const float* Wf  = (const float*)d_in[20], *bf  = (const float*)d_in[21];
    const float* gate = (const float*)d_in[22];
    const float* ln_g = (const float*)d_in[23];
    const float* ln_b = (const float*)d_in[24];

    float *Q, *Ks, *Vs, *Ka, *Va, *Kt, *Vt, *y;
    __nv_bfloat16 *Whi, *Wlo, *xh, *xl, *hadh, *hadl, *hth, *htl, *ath, *atl, *ynh, *ynl;
    cudaGetSymbolAddress((void**)&Q,    g_Q);
    cudaGetSymbolAddress((void**)&Ks,   g_Ks);
    cudaGetSymbolAddress((void**)&Vs,   g_Vs);
    cudaGetSymbolAddress((void**)&Ka,   g_Ka);
    cudaGetSymbolAddress((void**)&Va,   g_Va);
    cudaGetSymbolAddress((void**)&Kt,   g_Kt);
    cudaGetSymbolAddress((void**)&Vt,   g_Vt);
    cudaGetSymbolAddress((void**)&y,    g_y);
    cudaGetSymbolAddress((void**)&Whi,  g_Whi);
    cudaGetSymbolAddress((void**)&Wlo,  g_Wlo);
    cudaGetSymbolAddress((void**)&xh,   g_xh);
    cudaGetSymbolAddress((void**)&xl,   g_xl);
    cudaGetSymbolAddress((void**)&hadh, g_hadh);
    cudaGetSymbolAddress((void**)&hadl, g_hadl);
    cudaGetSymbolAddress((void**)&hth,  g_hth);
    cudaGetSymbolAddress((void**)&htl,  g_htl);
    cudaGetSymbolAddress((void**)&ath,  g_ath);
    cudaGetSymbolAddress((void**)&atl,  g_atl);
    cudaGetSymbolAddress((void**)&ynh,  g_ynh);
    cudaGetSymbolAddress((void**)&ynl,  g_ynl);

    cudaFuncSetAttribute(wgemm_k, cudaFuncAttributeMaxDynamicSharedMemorySize, SM_TOTAL);

    rope_init_k<<<(512 * 112 + 255) / 256, 256>>>();

    WPtrs wp;
    wp.w[0] = Wq; wp.w[1] = Wks; wp.w[2] = Wvs; wp.w[3] = Wka; wp.w[4] = Wva;
    wp.w[5] = Wkt; wp.w[6] = Wvt; wp.w[7] = Wo; wp.w[8] = Wf;
    convw_k<<<dim3(28, 28, 9), dim3(32, 8)>>>(wp);

    split_k<<<(512 * 224 + 255) / 256, 256>>>(x, xh, xl, 512 * 224);
    split_k<<<(32768 * 224 + 255) / 256, 256>>>(h_t, hth, htl, 32768 * 224);
    build_had_k<<<(4224 * 224 + 255) / 256, 256>>>(h_a, p);

    const size_t WS = 896 * 896;

    // QKV-self: A=x, W slabs 0..2
    {
        OutD od;
        od.out[0] = Q;  od.bias[0] = bq;  od.epi[0] = 1; od.rl[0] = 8;
        od.out[1] = Ks; od.bias[1] = bks; od.epi[1] = 1; od.rl[1] = 8;
        od.out[2] = Vs; od.bias[2] = bvs; od.epi[2] = 0; od.rl[2] = 1;
        od.res = nullptr;
        wgemm_k<<<dim3(21, 4), 256, SM_TOTAL>>>(xh, xl, Whi, Wlo, od, 512);
    }
    // Ka/Va: A=had, W slabs 3..4
    {
        OutD od;
        od.out[0] = Ka; od.bias[0] = bka; od.epi[0] = 1; od.rl[0] = 65;
        od.out[1] = Va; od.bias[1] = bva; od.epi[1] = 0; od.rl[1] = 1;
        od.out[2] = nullptr; od.bias[2] = nullptr; od.epi[2] = 0; od.rl[2] = 1;
        od.res = nullptr;
        wgemm_k<<<dim3(14, 33), 256, SM_TOTAL>>>(hadh, hadl, Whi + 3 * WS, Wlo + 3 * WS, od, 4160);
    }
    // Kt/Vt: A=h_t, W slabs 5..6
    {
        OutD od;
        od.out[0] = Kt; od.bias[0] = bkt; od.epi[0] = 1; od.rl[0] = 512;
        od.out[1] = Vt; od.bias[1] = bvt; od.epi[1] = 0; od.rl[1] = 1;
        od.out[2] = nullptr; od.bias[2] = nullptr; od.epi[2] = 0; od.rl[2] = 1;
        od.res = nullptr;
        wgemm_k<<<dim3(14, 256), 256, SM_TOTAL>>>(hth, htl, Whi + 5 * WS, Wlo + 5 * WS, od, 32768);
    }

    attn_k<<<512, 256>>>(gate);

    // Wo: +bias +residual(x) -> y
    {
        OutD od;
        od.out[0] = y; od.bias[0] = bo; od.epi[0] = 2; od.rl[0] = 1;
        od.out[1] = nullptr; od.bias[1] = nullptr; od.epi[1] = 0; od.rl[1] = 1;
        od.out[2] = nullptr; od.bias[2] = nullptr; od.epi[2] = 0; od.rl[2] = 1;
        od.res = x;
        wgemm_k<<<dim3(7, 4), 256, SM_TOTAL>>>(ath, atl, Whi + 7 * WS, Wlo + 7 * WS, od, 512);
    }

    ln_k<<<512, 256>>>(ln_g, ln_b);

    // Wf: +bias, ReLU -> d_out
    {
        OutD od;
        od.out[0] = (float*)d_out; od.bias[0] = bf; od.epi[0] = 3; od.rl[0] = 1;
        od.out[1] = nullptr; od.bias[1] = nullptr; od.epi[1] = 0; od.rl[1] = 1;
        od.out[2] = nullptr; od.bias[2] = nullptr; od.epi[2] = 0; od.rl[2] = 1;
        od.res = nullptr;
        wgemm_k<<<dim3(7, 4), 256, SM_TOTAL>>>(ynh, ynl, Whi + 8 * WS, Wlo + 8 * WS, od, 512);
    }
}

// round 5
// speedup vs baseline: 2.6006x; 1.2032x over previous
#include <cuda_runtime.h>
#include <cuda_bf16.h>
#include <cstdint>

#define DIMN 896
#define NKEYS 585

// ==================== device scratch (no allocation) ========================
__device__ float  g_Q   [512   * 896];
__device__ float  g_Ks  [512   * 896];
__device__ float  g_Vs  [512   * 896];
__device__ float  g_Ka  [4160  * 896];
__device__ float  g_Va  [4160  * 896];
__device__ float  g_Kt  [32768 * 896];
__device__ float  g_Vt  [32768 * 896];
__device__ float  g_y   [512   * 896];
__device__ float2 g_rope[512 * 112];
__device__ __nv_bfloat16 g_Whi[9][896 * 896];   // W^T hi  [n][k]
__device__ __nv_bfloat16 g_Wlo[9][896 * 896];   // W^T lo  [n][k]
// pre-split activations (hi/lo bf16)
__device__ __nv_bfloat16 g_xh   [512   * 896], g_xl   [512   * 896];
__device__ __nv_bfloat16 g_hadh [4224  * 896], g_hadl [4224  * 896];
__device__ __nv_bfloat16 g_hth  [32768 * 896], g_htl  [32768 * 896];
__device__ __nv_bfloat16 g_ath  [512   * 896], g_atl  [512   * 896];
__device__ __nv_bfloat16 g_ynh  [512   * 896], g_ynl  [512   * 896];

// ==================== helpers ===============================================
__device__ __forceinline__ uint32_t smem_u32(const void* p) {
    uint32_t a;
    asm("{ .reg .u64 t; cvta.to.shared.u64 t, %1; cvt.u32.u64 %0, t; }" : "=r"(a) : "l"(p));
    return a;
}
#define CP_ASYNC16(dst, src) asm volatile("cp.async.cg.shared.global [%0], [%1], 16;" :: "r"(dst), "l"(src))
#define CP_COMMIT()          asm volatile("cp.async.commit_group;" ::: "memory")
#define CP_WAIT0()           asm volatile("cp.async.wait_group 0;" ::: "memory")

#define LDSM4(r0, r1, r2, r3, addr) \
    asm volatile("ldmatrix.sync.aligned.m8n8.x4.shared.b16 {%0,%1,%2,%3}, [%4];" \
        : "=r"(r0), "=r"(r1), "=r"(r2), "=r"(r3) : "r"(addr))

#define MMA_BF16(d, a, b0, b1) \
    asm volatile("mma.sync.aligned.m16n8k16.row.col.f32.bf16.bf16.f32 " \
        "{%0,%1,%2,%3}, {%4,%5,%6,%7}, {%8,%9}, {%0,%1,%2,%3};" \
        : "+f"((d)[0]), "+f"((d)[1]), "+f"((d)[2]), "+f"((d)[3]) \
        : "r"((a)[0]), "r"((a)[1]), "r"((a)[2]), "r"((a)[3]), "r"(b0), "r"(b1))

__device__ __forceinline__ void split4(float4 v, uint2& hp, uint2& lp) {
    __nv_bfloat16 hx = __float2bfloat16_rn(v.x), hy = __float2bfloat16_rn(v.y);
    __nv_bfloat16 hz = __float2bfloat16_rn(v.z), hw = __float2bfloat16_rn(v.w);
    __nv_bfloat16 lx = __float2bfloat16_rn(v.x - __bfloat162float(hx));
    __nv_bfloat16 ly = __float2bfloat16_rn(v.y - __bfloat162float(hy));
    __nv_bfloat16 lz = __float2bfloat16_rn(v.z - __bfloat162float(hz));
    __nv_bfloat16 lw = __float2bfloat16_rn(v.w - __bfloat162float(hw));
    hp = make_uint2(((uint32_t)__bfloat16_as_ushort(hy) << 16) | __bfloat16_as_ushort(hx),
                    ((uint32_t)__bfloat16_as_ushort(hw) << 16) | __bfloat16_as_ushort(hz));
    lp = make_uint2(((uint32_t)__bfloat16_as_ushort(ly) << 16) | __bfloat16_as_ushort(lx),
                    ((uint32_t)__bfloat16_as_ushort(lw) << 16) | __bfloat16_as_ushort(lz));
}

// ==================== small prep kernels ====================================
__global__ void rope_init_k() {
    int i = blockIdx.x * blockDim.x + threadIdx.x;
    if (i >= 512 * 112) return;
    int pos = i / 112, d = i % 112, f = d % 56;
    float inv = powf(10000.0f, -((float)(2 * f) / 112.0f));
    float ang = (float)pos * inv;
    g_rope[i] = make_float2(cosf(ang), sinf(ang));
}

__global__ void split_k(const float* __restrict__ src, __nv_bfloat16* __restrict__ hi,
                        __nv_bfloat16* __restrict__ lo, int n4)
{
    int i = blockIdx.x * blockDim.x + threadIdx.x;
    if (i >= n4) return;
    float4 v = ((const float4*)src)[i];
    uint2 hp, lp;
    split4(v, hp, lp);
    ((uint2*)hi)[i] = hp;
    ((uint2*)lo)[i] = lp;
}

// build h_ad = concat(h_a, p) -> hi/lo bf16, padded to 4224 rows (zeros)
__global__ void build_had_k(const float* __restrict__ h_a, const float* __restrict__ p) {
    int i = blockIdx.x * blockDim.x + threadIdx.x;
    if (i >= 4224 * 224) return;
    int row = i / 224, c4 = i % 224;
    float4 v = make_float4(0.f, 0.f, 0.f, 0.f);
    if (row < 4160) {
        int b = row / 65, l = row % 65;
        v = (l < 64) ? ((const float4*)(h_a + ((size_t)(b * 64 + l)) * 896))[c4]
                     : ((const float4*)(p   + (size_t)b * 896))[c4];
    }
    uint2 hp, lp;
    split4(v, hp, lp);
    ((uint2*)g_hadh)[i] = hp;
    ((uint2*)g_hadl)[i] = lp;
}

struct WPtrs { const float* w[9]; };
// transpose + bf16 hi/lo split of all 9 weights: W[k][n] -> Whi/Wlo[n][k]
__global__ void convw_k(WPtrs wp) {
    __shared__ float tile[32][33];
    int wi = blockIdx.z;
    const float* W = wp.w[wi];
    __nv_bfloat16* hi = g_Whi[wi];
    __nv_bfloat16* lo = g_Wlo[wi];
    int tx = threadIdx.x, ty = threadIdx.y;
    int k0 = blockIdx.y * 32, n0 = blockIdx.x * 32;
    #pragma unroll
    for (int i = 0; i < 4; i++)
        tile[ty + i * 8][tx] = W[(size_t)(k0 + ty + i * 8) * 896 + n0 + tx];
    __syncthreads();
    #pragma unroll
    for (int i = 0; i < 4; i++) {
        int n = n0 + ty + i * 8, k = k0 + tx;
        float v = tile[tx][ty + i * 8];
        __nv_bfloat16 h = __float2bfloat16_rn(v);
        float r = v - __bfloat162float(h);
        hi[(size_t)n * 896 + k] = h;
        lo[(size_t)n * 896 + k] = __float2bfloat16_rn(r);
    }
}

// ==================== batched warp-mma bf16-split GEMM ======================
// CTA tile 128x128x32, 8 warps (4Mx2N), 2-stage cp.async pipeline, occ 2.
// stage layout (bytes): Ahi 0, Alo 10240, Bhi 20480, Blo 30720; stage=40960
#define LDAB 80
#define STAGE_B 40960
#define SM_TOTAL (2 * STAGE_B)

struct GB {
    const __nv_bfloat16 *Ahi, *Alo, *Bhi, *Blo;
    int M, ncol;
    float* out[3];
    const float* bias[3];
    int epi[3];     // 0 bias; 1 bias+RoPE; 2 bias+res; 3 bias+ReLU
    int rl[3];
    const float* res;
};
struct GB3 { GB g[3]; int b0, b1; };

__device__ __forceinline__ void stage_load(
    uint32_t s0, const __nv_bfloat16* __restrict__ Ahi, const __nv_bfloat16* __restrict__ Alo,
    const __nv_bfloat16* __restrict__ Bhi, const __nv_bfloat16* __restrict__ Blo,
    int row0, int col0, int kt, int tid)
{
    #pragma unroll
    for (int i = 0; i < 8; i++) {
        const int sel = i >> 1;
        int cc = (i & 1) * 256 + tid;
        int r = cc >> 2, ks = cc & 3;
        const __nv_bfloat16* base = (sel == 0) ? Ahi : (sel == 1) ? Alo : (sel == 2) ? Bhi : Blo;
        int rowg = (sel < 2) ? (row0 + r) : (col0 + r);
        uint32_t dst = s0 + (uint32_t)sel * 10240u + (uint32_t)(r * LDAB + ks * 16);
        CP_ASYNC16(dst, base + (size_t)rowg * 896 + kt + ks * 8);
    }
}

__global__ __launch_bounds__(256, 2) void wgemm_k(GB3 gb)
{
    extern __shared__ __align__(128) char smx[];
    const int id = blockIdx.x;
    const int gi = (id < gb.b0) ? 0 : (id < gb.b1) ? 1 : 2;
    const int local = id - ((gi == 0) ? 0 : (gi == 1) ? gb.b0 : gb.b1);
    const GB& G = gb.g[gi];
    const int colTile = local % G.ncol;
    const int row0 = (local / G.ncol) * 128;
    const int col0 = colTile * 128;

    const int tid  = threadIdx.x;
    const int lane = tid & 31, wid = tid >> 5;
    const int wm = (wid & 3) * 32, wn = (wid >> 2) * 64;
    uint32_t sb = smem_u32(smx);

    float acc[2][8][4];
    #pragma unroll
    for (int mi = 0; mi < 2; mi++)
        #pragma unroll
        for (int nj = 0; nj < 8; nj++)
            #pragma unroll
            for (int q = 0; q < 4; q++) acc[mi][nj][q] = 0.0f;

    const int a_r = lane & 15;
    const int a_k = (lane >> 4) * 16;
    const int b_r = (lane & 7) + ((lane >> 4) & 1) * 8;
    const int b_k = ((lane >> 3) & 1) * 16;

    stage_load(sb, G.Ahi, G.Alo, G.Bhi, G.Blo, row0, col0, 0, tid);
    CP_COMMIT();

    #pragma unroll 1
    for (int t = 0; t < 28; t++) {
        CP_WAIT0();
        __syncthreads();          // data t ready; all warps done computing t-1
        if (t + 1 < 28) {
            stage_load(sb + ((t + 1) & 1) * STAGE_B, G.Ahi, G.Alo, G.Bhi, G.Blo,
                       row0, col0, (t + 1) * 32, tid);
            CP_COMMIT();
        }
        uint32_t s0 = sb + (t & 1) * STAGE_B;
        uint32_t aHiB = s0 +         (uint32_t)((wm + a_r) * LDAB + a_k);
        uint32_t aLoB = aHiB + 10240;
        uint32_t bHiB = s0 + 20480 + (uint32_t)((wn + b_r) * LDAB + b_k);
        uint32_t bLoB = bHiB + 10240;
        #pragma unroll
        for (int ks = 0; ks < 2; ks++) {
            const uint32_t ksb = ks * 32;
            uint32_t ah[2][4], al[2][4], bh[8][2], bl[8][2];
            #pragma unroll
            for (int mi = 0; mi < 2; mi++) {
                LDSM4(ah[mi][0], ah[mi][1], ah[mi][2], ah[mi][3], aHiB + mi * (16 * LDAB) + ksb);
                LDSM4(al[mi][0], al[mi][1], al[mi][2], al[mi][3], aLoB + mi * (16 * LDAB) + ksb);
            }
            #pragma unroll
            for (int p = 0; p < 4; p++) {
                LDSM4(bh[2*p][0], bh[2*p][1], bh[2*p+1][0], bh[2*p+1][1], bHiB + p * (16 * LDAB) + ksb);
                LDSM4(bl[2*p][0], bl[2*p][1], bl[2*p+1][0], bl[2*p+1][1], bLoB + p * (16 * LDAB) + ksb);
            }
            #pragma unroll
            for (int mi = 0; mi < 2; mi++)
                #pragma unroll
                for (int nj = 0; nj < 8; nj++)
                    MMA_BF16(acc[mi][nj], ah[mi], bh[nj][0], bh[nj][1]);
            #pragma unroll
            for (int mi = 0; mi < 2; mi++)
                #pragma unroll
                for (int nj = 0; nj < 8; nj++)
                    MMA_BF16(acc[mi][nj], ah[mi], bl[nj][0], bl[nj][1]);
            #pragma unroll
            for (int mi = 0; mi < 2; mi++)
                #pragma unroll
                for (int nj = 0; nj < 8; nj++)
                    MMA_BF16(acc[mi][nj], al[mi], bh[nj][0], bh[nj][1]);
        }
        __syncthreads();          // all warps done with stage t before it is reloaded
    }

    // ---------------- epilogue ----------------
    const int cb = colTile / 7;
    const int lcol0 = (colTile % 7) * 128;
    float* Co = G.out[cb];
    const float* bias = G.bias[cb];
    const int epi = G.epi[cb];
    const int ropeL = G.rl[cb];

    #pragma unroll
    for (int mi = 0; mi < 2; mi++) {
        #pragma unroll
        for (int half = 0; half < 2; half++) {
            int row = row0 + wm + mi * 16 + (lane >> 2) + half * 8;
            if (row >= G.M) continue;
            float* crow = Co + (size_t)row * DIMN;
            const float2* rt = (epi == 1) ? (g_rope + (size_t)(row % ropeL) * 112) : nullptr;
            const float* rrow = (epi == 2) ? (G.res + (size_t)row * DIMN) : nullptr;
            #pragma unroll
            for (int nj = 0; nj < 8; nj++) {
                int gc = lcol0 + wn + nj * 8 + (lane & 3) * 2;
                float v0 = acc[mi][nj][half * 2]     + bias[gc];
                float v1 = acc[mi][nj][half * 2 + 1] + bias[gc + 1];
                float2 o;
                if (epi == 1) {
                    int d = gc % 112;
                    float2 r0 = rt[d], r1 = rt[d + 1];
                    o.x = v0 * r0.x - v1 * r0.y;
                    o.y = v1 * r1.x + v0 * r1.y;
                } else if (epi == 2) {
                    o.x = v0 + rrow[gc]; o.y = v1 + rrow[gc + 1];
                } else if (epi == 3) {
                    o.x = fmaxf(v0, 0.f); o.y = fmaxf(v1, 0.f);
                } else {
                    o.x = v0; o.y = v1;
                }
                *(float2*)(crow + gc) = o;
            }
        }
    }
}

// ==================== attention (emits hi/lo bf16) ==========================
__global__ __launch_bounds__(256) void attn_k(const float* __restrict__ gate)
{
    const int b = blockIdx.x >> 3, h = blockIdx.x & 7;
    __shared__ float q_s[8][112];
    __shared__ float w_s[8][592];
    __shared__ const float* kp[NKEYS];
    __shared__ const float* vp[NKEYS];
    const int tid = threadIdx.x;

    for (int i = tid; i < 8 * 112; i += 256) {
        int r = i / 112, d = i % 112;
        q_s[r][d] = g_Q[((size_t)(b * 8 + r)) * 896 + h * 112 + d];
    }
    for (int k = tid; k < NKEYS; k += 256) {
        size_t o;
        const float *kb, *vb;
        if (k < 8)       { o = ((size_t)(b * 8 + k)) * 896 + h * 112;          kb = g_Ks + o; vb = g_Vs + o; }
        else if (k < 73) { o = ((size_t)(b * 65 + (k - 8))) * 896 + h * 112;   kb = g_Ka + o; vb = g_Va + o; }
        else             { o = ((size_t)(b * 512 + (k - 73))) * 896 + h * 112; kb = g_Kt + o; vb = g_Vt + o; }
        kp[k] = kb; vp[k] = vb;
    }
    __syncthreads();

    const float ratio = tanhf(gate[0]);
    const float sc0   = rsqrtf(112.0f);

    for (int k = tid; k < NKEYS; k += 256) {
        const float* kb = kp[k];
        float acc[8] = {0.f, 0.f, 0.f, 0.f, 0.f, 0.f, 0.f, 0.f};
        #pragma unroll 4
        for (int d4 = 0; d4 < 28; ++d4) {
            float4 kv = *(const float4*)(kb + d4 * 4);
            #pragma unroll
            for (int r = 0; r < 8; r++) {
                acc[r] = fmaf(q_s[r][d4 * 4 + 0], kv.x, acc[r]);
                acc[r] = fmaf(q_s[r][d4 * 4 + 1], kv.y, acc[r]);
                acc[r] = fmaf(q_s[r][d4 * 4 + 2], kv.z, acc[r]);
                acc[r] = fmaf(q_s[r][d4 * 4 + 3], kv.w, acc[r]);
            }
        }
        float sc = (k < 73) ? sc0 : sc0 * ratio;
        #pragma unroll
        for (int r = 0; r < 8; r++) w_s[r][k] = acc[r] * sc;
    }
    __syncthreads();

    {
        int r = tid >> 5, lane = tid & 31;
        float m = -3.0e38f;
        for (int k = lane; k < NKEYS; k += 32) m = fmaxf(m, w_s[r][k]);
        #pragma unroll
        for (int o = 16; o; o >>= 1) m = fmaxf(m, __shfl_xor_sync(0xffffffffu, m, o));
        float s = 0.0f;
        for (int k = lane; k < NKEYS; k += 32) { float e = __expf(w_s[r][k] - m); w_s[r][k] = e; s += e; }
        #pragma unroll
        for (int o = 16; o; o >>= 1) s += __shfl_xor_sync(0xffffffffu, s, o);
        float inv = 1.0f / s;
        for (int k = lane; k < NKEYS; k += 32) w_s[r][k] *= inv;
    }
    __syncthreads();

    for (int idx = tid; idx < 896; idx += 256) {
        int r = idx / 112, d = idx % 112;
        float acc = 0.0f;
        #pragma unroll 4
        for (int k = 0; k < NKEYS; k++) acc = fmaf(w_s[r][k], vp[k][d], acc);
        size_t oidx = ((size_t)(b * 8 + r)) * 896 + h * 112 + d;
        __nv_bfloat16 hv = __float2bfloat16_rn(acc);
        g_ath[oidx] = hv;
        g_atl[oidx] = __float2bfloat16_rn(acc - __bfloat162float(hv));
    }
}

// ==================== layernorm (emits hi/lo bf16) ==========================
__global__ __launch_bounds__(256) void ln_k(const float* __restrict__ g,
                                            const float* __restrict__ bt)
{
    int row = blockIdx.x;
    const float* y = g_y + (size_t)row * 896;
    int tid = threadIdx.x;
    float s = 0.0f, s2 = 0.0f;
    for (int j = tid; j < 896; j += 256) { float v = y[j]; s += v; s2 += v * v; }
    __shared__ float rs[8], rs2[8];
    #pragma unroll
    for (int o = 16; o; o >>= 1) { s += __shfl_xor_sync(~0u, s, o); s2 += __shfl_xor_sync(~0u, s2, o); }
    if ((tid & 31) == 0) { rs[tid >> 5] = s; rs2[tid >> 5] = s2; }
    __syncthreads();
    if (tid < 32) {
        s  = (tid < 8) ? rs[tid]  : 0.0f;
        s2 = (tid < 8) ? rs2[tid] : 0.0f;
        #pragma unroll
        for (int o = 4; o; o >>= 1) { s += __shfl_xor_sync(~0u, s, o); s2 += __shfl_xor_sync(~0u, s2, o); }
        if (tid == 0) { rs[0] = s; rs2[0] = s2; }
    }
    __syncthreads();
    float mu  = rs[0]  * (1.0f / 896.0f);
    float var = rs2[0] * (1.0f / 896.0f) - mu * mu;
    float inv = rsqrtf(var + 1e-5f);
    for (int j = tid; j < 896; j += 256) {
        float v = (y[j] - mu) * inv * g[j] + bt[j];
        __nv_bfloat16 hv = __float2bfloat16_rn(v);
        g_ynh[(size_t)row * 896 + j] = hv;
        g_ynl[(size_t)row * 896 + j] = __float2bfloat16_rn(v - __bfloat162float(hv));
    }
}

// ==================== host orchestration ====================================
extern "C" void kernel_launch(void* const* d_in, const int* in_sizes, int n_in,
                              void* d_out, int out_size)
{
    const float* x   = (const float*)d_in[0];
    const float* h_a = (const float*)d_in[1];
    const float* h_t = (const float*)d_in[2];
    const float* p   = (const float*)d_in[3];
    const float* Wq  = (const float*)d_in[4],  *bq  = (const float*)d_in[5];
    const float* Wks = (const float*)d_in[6],  *bks = (const float*)d_in[7];
    const float* Wvs = (const float*)d_in[8],  *bvs = (const float*)d_in[9];
    const float* Wka = (const float*)d_in[10], *bka = (const float*)d_in[11];
    const float* Wva = (const float*)d_in[12], *bva = (const float*)d_in[13];
    const float* Wkt = (const float*)d_in[14], *bkt = (const float*)d_in[15];
    const float* Wvt = (const float*)d_in[16], *bvt = (const float*)d_in[17];
    const float* Wo  = (const float*)d_in[18], *bo  = (const float*)d_in[19];
    const float* Wf  = (const float*)d_in[20], *bf  = (const float*)d_in[21];
    const float* gate = (const float*)d_in[22];
    const float* ln_g = (const float*)d_in[23];
    const float* ln_b = (const float*)d_in[24];

    float *Q, *Ks, *Vs, *Ka, *Va, *Kt, *Vt, *y;
    __nv_bfloat16 *Whi, *Wlo, *xh, *xl, *hadh, *hadl, *hth, *htl, *ath, *atl, *ynh, *ynl;
    cudaGetSymbolAddress((void**)&Q,    g_Q);
    cudaGetSymbolAddress((void**)&Ks,   g_Ks);
    cudaGetSymbolAddress((void**)&Vs,   g_Vs);
    cudaGetSymbolAddress((void**)&Ka,   g_Ka);
    cudaGetSymbolAddress((void**)&Va,   g_Va);
    cudaGetSymbolAddress((void**)&Kt,   g_Kt);
    cudaGetSymbolAddress((void**)&Vt,   g_Vt);
    cudaGetSymbolAddress((void**)&y,    g_y);
    cudaGetSymbolAddress((void**)&Whi,  g_Whi);
    cudaGetSymbolAddress((void**)&Wlo,  g_Wlo);
    cudaGetSymbolAddress((void**)&xh,   g_xh);
    cudaGetSymbolAddress((void**)&xl,   g_xl);
    cudaGetSymbolAddress((void**)&hadh, g_hadh);
    cudaGetSymbolAddress((void**)&hadl, g_hadl);
    cudaGetSymbolAddress((void**)&hth,  g_hth);
    cudaGetSymbolAddress((void**)&htl,  g_htl);
    cudaGetSymbolAddress((void**)&ath,  g_ath);
    cudaGetSymbolAddress((void**)&atl,  g_atl);
    cudaGetSymbolAddress((void**)&ynh,  g_ynh);
    cudaGetSymbolAddress((void**)&ynl,  g_ynl);

    cudaFuncSetAttribute(wgemm_k, cudaFuncAttributeMaxDynamicSharedMemorySize, STAGE_B * 2);

    rope_init_k<<<(512 * 112 + 255) / 256, 256>>>();

    WPtrs wp;
    wp.w[0] = Wq; wp.w[1] = Wks; wp.w[2] = Wvs; wp.w[3] = Wka; wp.w[4] = Wva;
    wp.w[5] = Wkt; wp.w[6] = Wvt; wp.w[7] = Wo; wp.w[8] = Wf;
    convw_k<<<dim3(28, 28, 9), dim3(32, 8)>>>(wp);

    split_k<<<(512 * 224 + 255) / 256, 256>>>(x, xh, xl, 512 * 224);
    split_k<<<(32768 * 224 + 255) / 256, 256>>>(h_t, hth, htl, 32768 * 224);
    build_had_k<<<(4224 * 224 + 255) / 256, 256>>>(h_a, p);

    const size_t WS = 896 * 896;

    // ---- one batched launch: Kt/Vt (3584) + Ka/Va (462) + QKV (84) --------
    {
        GB3 gb;
        // group 0: Kt/Vt  (slabs 5,6), M=32768, ncol=14
        gb.g[0].Ahi = hth; gb.g[0].Alo = htl;
        gb.g[0].Bhi = Whi + 5 * WS; gb.g[0].Blo = Wlo + 5 * WS;
        gb.g[0].M = 32768; gb.g[0].ncol = 14;
        gb.g[0].out[0] = Kt; gb.g[0].bias[0] = bkt; gb.g[0].epi[0] = 1; gb.g[0].rl[0] = 512;
        gb.g[0].out[1] = Vt; gb.g[0].bias[1] = bvt; gb.g[0].epi[1] = 0; gb.g[0].rl[1] = 1;
        gb.g[0].out[2] = nullptr; gb.g[0].bias[2] = nullptr; gb.g[0].epi[2] = 0; gb.g[0].rl[2] = 1;
        gb.g[0].res = nullptr;
        // group 1: Ka/Va (slabs 3,4), M=4160, ncol=14
        gb.g[1].Ahi = hadh; gb.g[1].Alo = hadl;
        gb.g[1].Bhi = Whi + 3 * WS; gb.g[1].Blo = Wlo + 3 * WS;
        gb.g[1].M = 4160; gb.g[1].ncol = 14;
        gb.g[1].out[0] = Ka; gb.g[1].bias[0] = bka; gb.g[1].epi[0] = 1; gb.g[1].rl[0] = 65;
        gb.g[1].out[1] = Va; gb.g[1].bias[1] = bva; gb.g[1].epi[1] = 0; gb.g[1].rl[1] = 1;
        gb.g[1].out[2] = nullptr; gb.g[1].bias[2] = nullptr; gb.g[1].epi[2] = 0; gb.g[1].rl[2] = 1;
        gb.g[1].res = nullptr;
        // group 2: QKV-self (slabs 0..2), M=512, ncol=21
        gb.g[2].Ahi = xh; gb.g[2].Alo = xl;
        gb.g[2].Bhi = Whi; gb.g[2].Blo = Wlo;
        gb.g[2].M = 512; gb.g[2].ncol = 21;
        gb.g[2].out[0] = Q;  gb.g[2].bias[0] = bq;  gb.g[2].epi[0] = 1; gb.g[2].rl[0] = 8;
        gb.g[2].out[1] = Ks; gb.g[2].bias[1] = bks; gb.g[2].epi[1] = 1; gb.g[2].rl[1] = 8;
        gb.g[2].out[2] = Vs; gb.g[2].bias[2] = bvs; gb.g[2].epi[2] = 0; gb.g[2].rl[2] = 1;
        gb.g[2].res = nullptr;
        gb.b0 = 3584; gb.b1 = 3584 + 462;
        wgemm_k<<<3584 + 462 + 84, 256, SM_TOTAL>>>(gb);
    }

    attn_k<<<512, 256>>>(gate);

    // ---- Wo: +bias +residual(x) -> y ---------------------------------------
    {
        GB3 gb;
        gb.g[0].Ahi = ath; gb.g[0].Alo = atl;
        gb.g[0].Bhi = Whi + 7 * WS; gb.g[0].Blo = Wlo + 7 * WS;
        gb.g[0].M = 512; gb.g[0].ncol = 7;
        gb.g[0].out[0] = y; gb.g[0].bias[0] = bo; gb.g[0].epi[0] = 2; gb.g[0].rl[0] = 1;
        gb.g[0].out[1] = nullptr; gb.g[0].bias[1] = nullptr; gb.g[0].epi[1] = 0; gb.g[0].rl[1] = 1;
        gb.g[0].out[2] = nullptr; gb.g[0].bias[2] = nullptr; gb.g[0].epi[2] = 0; gb.g[0].rl[2] = 1;
        gb.g[0].res = x;
        gb.g[1] = gb.g[0]; gb.g[2] = gb.g[0];
        gb.b0 = 1 << 30; gb.b1 = 1 << 30;
        wgemm_k<<<28, 256, SM_TOTAL>>>(gb);
    }

    ln_k<<<512, 256>>>(ln_g, ln_b);

    // ---- Wf: +bias, ReLU -> d_out ------------------------------------------
    {
        GB3 gb;
        gb.g[0].Ahi = ynh; gb.g[0].Alo = ynl;
        gb.g[0].Bhi = Whi + 8 * WS; gb.g[0].Blo = Wlo + 8 * WS;
        gb.g[0].M = 512; gb.g[0].ncol = 7;
        gb.g[0].out[0] = (float*)d_out; gb.g[0].bias[0] = bf; gb.g[0].epi[0] = 3; gb.g[0].rl[0] = 1;
        gb.g[0].out[1] = nullptr; gb.g[0].bias[1] = nullptr; gb.g[0].epi[1] = 0; gb.g[0].rl[1] = 1;
        gb.g[0].out[2] = nullptr; gb.g[0].bias[2] = nullptr; gb.g[0].epi[2] = 0; gb.g[0].rl[2] = 1;
        gb.g[0].res = nullptr;
        gb.g[1] = gb.g[0]; gb.g[2] = gb.g[0];
        gb.b0 = 1 << 30; gb.b1 = 1 << 30;
        wgemm_k<<<28, 256, SM_TOTAL>>>(gb);
    }
}

// round 6
// speedup vs baseline: 3.2159x; 1.2366x over previous
#include <cuda_runtime.h>
#include <cuda_fp16.h>
#include <cstdint>

#define DIMN 896
#define NKEYS 585

// ==================== device scratch (no allocation) ========================
__device__ float  g_Q   [512   * 896];
__device__ float  g_Ks  [512   * 896];
__device__ float  g_Vs  [512   * 896];
__device__ float  g_Ka  [4160  * 896];
__device__ float  g_Va  [4160  * 896];
__device__ float  g_Kt  [32768 * 896];
__device__ float  g_Vt  [32768 * 896];
__device__ float  g_y   [512   * 896];
__device__ float2 g_rope[512 * 112];
__device__ __half g_Whi[9][896 * 896];   // W^T hi  [n][k]
__device__ __half g_Wlo[9][896 * 896];   // W^T lo  [n][k]
// fp16 activations (single precision copy; ~2^-12 rounding)
__device__ __half g_xh  [512   * 896];
__device__ __half g_hadh[4224  * 896];
__device__ __half g_hth [32768 * 896];
__device__ __half g_ath [512   * 896];
__device__ __half g_ynh [512   * 896];

// ==================== helpers ===============================================
__device__ __forceinline__ uint32_t smem_u32(const void* p) {
    uint32_t a;
    asm("{ .reg .u64 t; cvta.to.shared.u64 t, %1; cvt.u32.u64 %0, t; }" : "=r"(a) : "l"(p));
    return a;
}
#define CP_ASYNC16(dst, src) asm volatile("cp.async.cg.shared.global [%0], [%1], 16;" :: "r"(dst), "l"(src))
#define CP_COMMIT()          asm volatile("cp.async.commit_group;" ::: "memory")
#define CP_WAIT0()           asm volatile("cp.async.wait_group 0;" ::: "memory")

#define LDSM4(r0, r1, r2, r3, addr) \
    asm volatile("ldmatrix.sync.aligned.m8n8.x4.shared.b16 {%0,%1,%2,%3}, [%4];" \
        : "=r"(r0), "=r"(r1), "=r"(r2), "=r"(r3) : "r"(addr))

#define MMA_F16(d, a, b0, b1) \
    asm volatile("mma.sync.aligned.m16n8k16.row.col.f32.f16.f16.f32 " \
        "{%0,%1,%2,%3}, {%4,%5,%6,%7}, {%8,%9}, {%0,%1,%2,%3};" \
        : "+f"((d)[0]), "+f"((d)[1]), "+f"((d)[2]), "+f"((d)[3]) \
        : "r"((a)[0]), "r"((a)[1]), "r"((a)[2]), "r"((a)[3]), "r"(b0), "r"(b1))

__device__ __forceinline__ uint2 cvt4h(float4 v) {
    __half2 lo = __floats2half2_rn(v.x, v.y);
    __half2 hi = __floats2half2_rn(v.z, v.w);
    return make_uint2(*(uint32_t*)&lo, *(uint32_t*)&hi);
}

// ==================== small prep kernels ====================================
__global__ void rope_init_k() {
    int i = blockIdx.x * blockDim.x + threadIdx.x;
    if (i >= 512 * 112) return;
    int pos = i / 112, d = i % 112, f = d % 56;
    float inv = powf(10000.0f, -((float)(2 * f) / 112.0f));
    float ang = (float)pos * inv;
    g_rope[i] = make_float2(cosf(ang), sinf(ang));
}

__global__ void cvt_k(const float* __restrict__ src, __half* __restrict__ dst, int n4)
{
    int i = blockIdx.x * blockDim.x + threadIdx.x;
    if (i >= n4) return;
    ((uint2*)dst)[i] = cvt4h(((const float4*)src)[i]);
}

// build h_ad = concat(h_a, p) -> fp16, padded to 4224 rows (zeros)
__global__ void build_had_k(const float* __restrict__ h_a, const float* __restrict__ p) {
    int i = blockIdx.x * blockDim.x + threadIdx.x;
    if (i >= 4224 * 224) return;
    int row = i / 224, c4 = i % 224;
    float4 v = make_float4(0.f, 0.f, 0.f, 0.f);
    if (row < 4160) {
        int b = row / 65, l = row % 65;
        v = (l < 64) ? ((const float4*)(h_a + ((size_t)(b * 64 + l)) * 896))[c4]
                     : ((const float4*)(p   + (size_t)b * 896))[c4];
    }
    ((uint2*)g_hadh)[i] = cvt4h(v);
}

struct WPtrs { const float* w[9]; };
// transpose + fp16 hi/lo split of all 9 weights: W[k][n] -> Whi/Wlo[n][k]
__global__ void convw_k(WPtrs wp) {
    __shared__ float tile[32][33];
    int wi = blockIdx.z;
    const float* W = wp.w[wi];
    __half* hi = g_Whi[wi];
    __half* lo = g_Wlo[wi];
    int tx = threadIdx.x, ty = threadIdx.y;
    int k0 = blockIdx.y * 32, n0 = blockIdx.x * 32;
    #pragma unroll
    for (int i = 0; i < 4; i++)
        tile[ty + i * 8][tx] = W[(size_t)(k0 + ty + i * 8) * 896 + n0 + tx];
    __syncthreads();
    #pragma unroll
    for (int i = 0; i < 4; i++) {
        int n = n0 + ty + i * 8, k = k0 + tx;
        float v = tile[tx][ty + i * 8];
        __half h = __float2half_rn(v);
        float r = v - __half2float(h);
        hi[(size_t)n * 896 + k] = h;
        lo[(size_t)n * 896 + k] = __float2half_rn(r);
    }
}

// ==================== batched warp-mma fp16 2-pass GEMM =====================
// C = A(fp16) @ (Whi + Wlo): CTA tile 128x128x32, 8 warps, 2-stage, occ 2.
// stage layout (bytes): A 0, Bhi 10240, Blo 20480; stage=30720
#define LDAB 80
#define STAGE_B 30720
#define SM_TOTAL (2 * STAGE_B)

struct GB {
    const __half *Ah, *Bhi, *Blo;
    int M, ncol;
    float* out[3];
    const float* bias[3];
    int epi[3];     // 0 bias; 1 bias+RoPE; 2 bias+res; 3 bias+ReLU
    int rl[3];
    const float* res;
};
struct GB3 { GB g[3]; int b0, b1; };

__device__ __forceinline__ void stage_load(
    uint32_t s0, const __half* __restrict__ Ah,
    const __half* __restrict__ Bhi, const __half* __restrict__ Blo,
    int row0, int col0, int kt, int tid)
{
    #pragma unroll
    for (int i = 0; i < 6; i++) {
        const int sel = i >> 1;
        int cc = (i & 1) * 256 + tid;
        int r = cc >> 2, ks = cc & 3;
        const __half* base = (sel == 0) ? Ah : (sel == 1) ? Bhi : Blo;
        int rowg = (sel == 0) ? (row0 + r) : (col0 + r);
        uint32_t dst = s0 + (uint32_t)sel * 10240u + (uint32_t)(r * LDAB + ks * 16);
        CP_ASYNC16(dst, base + (size_t)rowg * 896 + kt + ks * 8);
    }
}

__global__ __launch_bounds__(256, 2) void wgemm_k(GB3 gb)
{
    extern __shared__ __align__(128) char smx[];
    const int id = blockIdx.x;
    const int gi = (id < gb.b0) ? 0 : (id < gb.b1) ? 1 : 2;
    const int local = id - ((gi == 0) ? 0 : (gi == 1) ? gb.b0 : gb.b1);
    const GB& G = gb.g[gi];
    const int colTile = local % G.ncol;
    const int row0 = (local / G.ncol) * 128;
    const int col0 = colTile * 128;

    const int tid  = threadIdx.x;
    const int lane = tid & 31, wid = tid >> 5;
    const int wm = (wid & 3) * 32, wn = (wid >> 2) * 64;
    uint32_t sb = smem_u32(smx);

    float acc[2][8][4];
    #pragma unroll
    for (int mi = 0; mi < 2; mi++)
        #pragma unroll
        for (int nj = 0; nj < 8; nj++)
            #pragma unroll
            for (int q = 0; q < 4; q++) acc[mi][nj][q] = 0.0f;

    const int a_r = lane & 15;
    const int a_k = (lane >> 4) * 16;
    const int b_r = (lane & 7) + ((lane >> 4) & 1) * 8;
    const int b_k = ((lane >> 3) & 1) * 16;

    stage_load(sb, G.Ah, G.Bhi, G.Blo, row0, col0, 0, tid);
    CP_COMMIT();

    #pragma unroll 1
    for (int t = 0; t < 28; t++) {
        CP_WAIT0();
        __syncthreads();          // stage t ready; all warps done with stage t-1
        if (t + 1 < 28) {
            stage_load(sb + ((t + 1) & 1) * STAGE_B, G.Ah, G.Bhi, G.Blo,
                       row0, col0, (t + 1) * 32, tid);
            CP_COMMIT();
        }
        uint32_t s0 = sb + (t & 1) * STAGE_B;
        uint32_t aB   = s0 +         (uint32_t)((wm + a_r) * LDAB + a_k);
        uint32_t bHiB = s0 + 10240 + (uint32_t)((wn + b_r) * LDAB + b_k);
        uint32_t bLoB = bHiB + 10240;
        #pragma unroll
        for (int ks = 0; ks < 2; ks++) {
            const uint32_t ksb = ks * 32;
            uint32_t a[2][4], bh[8][2], bl[8][2];
            #pragma unroll
            for (int mi = 0; mi < 2; mi++)
                LDSM4(a[mi][0], a[mi][1], a[mi][2], a[mi][3], aB + mi * (16 * LDAB) + ksb);
            #pragma unroll
            for (int p = 0; p < 4; p++) {
                LDSM4(bh[2*p][0], bh[2*p][1], bh[2*p+1][0], bh[2*p+1][1], bHiB + p * (16 * LDAB) + ksb);
                LDSM4(bl[2*p][0], bl[2*p][1], bl[2*p+1][0], bl[2*p+1][1], bLoB + p * (16 * LDAB) + ksb);
            }
            #pragma unroll
            for (int mi = 0; mi < 2; mi++)
                #pragma unroll
                for (int nj = 0; nj < 8; nj++)
                    MMA_F16(acc[mi][nj], a[mi], bh[nj][0], bh[nj][1]);
            #pragma unroll
            for (int mi = 0; mi < 2; mi++)
                #pragma unroll
                for (int nj = 0; nj < 8; nj++)
                    MMA_F16(acc[mi][nj], a[mi], bl[nj][0], bl[nj][1]);
        }
    }

    // ---------------- epilogue ----------------
    const int cb = colTile / 7;
    const int lcol0 = (colTile % 7) * 128;
    float* Co = G.out[cb];
    const float* bias = G.bias[cb];
    const int epi = G.epi[cb];
    const int ropeL = G.rl[cb];

    #pragma unroll
    for (int mi = 0; mi < 2; mi++) {
        #pragma unroll
        for (int half = 0; half < 2; half++) {
            int row = row0 + wm + mi * 16 + (lane >> 2) + half * 8;
            if (row >= G.M) continue;
            float* crow = Co + (size_t)row * DIMN;
            const float2* rt = (epi == 1) ? (g_rope + (size_t)(row % ropeL) * 112) : nullptr;
            const float* rrow = (epi == 2) ? (G.res + (size_t)row * DIMN) : nullptr;
            #pragma unroll
            for (int nj = 0; nj < 8; nj++) {
                int gc = lcol0 + wn + nj * 8 + (lane & 3) * 2;
                float v0 = acc[mi][nj][half * 2]     + bias[gc];
                float v1 = acc[mi][nj][half * 2 + 1] + bias[gc + 1];
                float2 o;
                if (epi == 1) {
                    int d = gc % 112;
                    float2 r0 = rt[d], r1 = rt[d + 1];
                    o.x = v0 * r0.x - v1 * r0.y;
                    o.y = v1 * r1.x + v0 * r1.y;
                } else if (epi == 2) {
                    o.x = v0 + rrow[gc]; o.y = v1 + rrow[gc + 1];
                } else if (epi == 3) {
                    o.x = fmaxf(v0, 0.f); o.y = fmaxf(v1, 0.f);
                } else {
                    o.x = v0; o.y = v1;
                }
                *(float2*)(crow + gc) = o;
            }
        }
    }
}

// ==================== attention (emits fp16) ================================
__global__ __launch_bounds__(256) void attn_k(const float* __restrict__ gate)
{
    const int b = blockIdx.x >> 3, h = blockIdx.x & 7;
    __shared__ float q_s[8][112];
    __shared__ float w_s[8][592];
    __shared__ const float* kp[NKEYS];
    __shared__ const float* vp[NKEYS];
    const int tid = threadIdx.x;

    for (int i = tid; i < 8 * 112; i += 256) {
        int r = i / 112, d = i % 112;
        q_s[r][d] = g_Q[((size_t)(b * 8 + r)) * 896 + h * 112 + d];
    }
    for (int k = tid; k < NKEYS; k += 256) {
        size_t o;
        const float *kb, *vb;
        if (k < 8)       { o = ((size_t)(b * 8 + k)) * 896 + h * 112;          kb = g_Ks + o; vb = g_Vs + o; }
        else if (k < 73) { o = ((size_t)(b * 65 + (k - 8))) * 896 + h * 112;   kb = g_Ka + o; vb = g_Va + o; }
        else             { o = ((size_t)(b * 512 + (k - 73))) * 896 + h * 112; kb = g_Kt + o; vb = g_Vt + o; }
        kp[k] = kb; vp[k] = vb;
    }
    __syncthreads();

    const float ratio = tanhf(gate[0]);
    const float sc0   = rsqrtf(112.0f);

    for (int k = tid; k < NKEYS; k += 256) {
        const float* kb = kp[k];
        float acc[8] = {0.f, 0.f, 0.f, 0.f, 0.f, 0.f, 0.f, 0.f};
        #pragma unroll 4
        for (int d4 = 0; d4 < 28; ++d4) {
            float4 kv = *(const float4*)(kb + d4 * 4);
            #pragma unroll
            for (int r = 0; r < 8; r++) {
                acc[r] = fmaf(q_s[r][d4 * 4 + 0], kv.x, acc[r]);
                acc[r] = fmaf(q_s[r][d4 * 4 + 1], kv.y, acc[r]);
                acc[r] = fmaf(q_s[r][d4 * 4 + 2], kv.z, acc[r]);
                acc[r] = fmaf(q_s[r][d4 * 4 + 3], kv.w, acc[r]);
            }
        }
        float sc = (k < 73) ? sc0 : sc0 * ratio;
        #pragma unroll
        for (int r = 0; r < 8; r++) w_s[r][k] = acc[r] * sc;
    }
    __syncthreads();

    {
        int r = tid >> 5, lane = tid & 31;
        float m = -3.0e38f;
        for (int k = lane; k < NKEYS; k += 32) m = fmaxf(m, w_s[r][k]);
        #pragma unroll
        for (int o = 16; o; o >>= 1) m = fmaxf(m, __shfl_xor_sync(0xffffffffu, m, o));
        float s = 0.0f;
        for (int k = lane; k < NKEYS; k += 32) { float e = __expf(w_s[r][k] - m); w_s[r][k] = e; s += e; }
        #pragma unroll
        for (int o = 16; o; o >>= 1) s += __shfl_xor_sync(0xffffffffu, s, o);
        float inv = 1.0f / s;
        for (int k = lane; k < NKEYS; k += 32) w_s[r][k] *= inv;
    }
    __syncthreads();

    for (int idx = tid; idx < 896; idx += 256) {
        int r = idx / 112, d = idx % 112;
        float acc = 0.0f;
        #pragma unroll 4
        for (int k = 0; k < NKEYS; k++) acc = fmaf(w_s[r][k], vp[k][d], acc);
        g_ath[((size_t)(b * 8 + r)) * 896 + h * 112 + d] = __float2half_rn(acc);
    }
}

// ==================== layernorm (emits fp16) ================================
__global__ __launch_bounds__(256) void ln_k(const float* __restrict__ g,
                                            const float* __restrict__ bt)
{
    int row = blockIdx.x;
    const float* y = g_y + (size_t)row * 896;
    int tid = threadIdx.x;
    float s = 0.0f, s2 = 0.0f;
    for (int j = tid; j < 896; j += 256) { float v = y[j]; s += v; s2 += v * v; }
    __shared__ float rs[8], rs2[8];
    #pragma unroll
    for (int o = 16; o; o >>= 1) { s += __shfl_xor_sync(~0u, s, o); s2 += __shfl_xor_sync(~0u, s2, o); }
    if ((tid & 31) == 0) { rs[tid >> 5] = s; rs2[tid >> 5] = s2; }
    __syncthreads();
    if (tid < 32) {
        s  = (tid < 8) ? rs[tid]  : 0.0f;
        s2 = (tid < 8) ? rs2[tid] : 0.0f;
        #pragma unroll
        for (int o = 4; o; o >>= 1) { s += __shfl_xor_sync(~0u, s, o); s2 += __shfl_xor_sync(~0u, s2, o); }
        if (tid == 0) { rs[0] = s; rs2[0] = s2; }
    }
    __syncthreads();
    float mu  = rs[0]  * (1.0f / 896.0f);
    float var = rs2[0] * (1.0f / 896.0f) - mu * mu;
    float inv = rsqrtf(var + 1e-5f);
    for (int j = tid; j < 896; j += 256)
        g_ynh[(size_t)row * 896 + j] = __float2half_rn((y[j] - mu) * inv * g[j] + bt[j]);
}

// ==================== host orchestration ====================================
extern "C" void kernel_launch(void* const* d_in, const int* in_sizes, int n_in,
                              void* d_out, int out_size)
{
    const float* x   = (const float*)d_in[0];
    const float* h_a = (const float*)d_in[1];
    const float* h_t = (const float*)d_in[2];
    const float* p   = (const float*)d_in[3];
    const float* Wq  = (const float*)d_in[4],  *bq  = (const float*)d_in[5];
    const float* Wks = (const float*)d_in[6],  *bks = (const float*)d_in[7];
    const float* Wvs = (const float*)d_in[8],  *bvs = (const float*)d_in[9];
    const float* Wka = (const float*)d_in[10], *bka = (const float*)d_in[11];
    const float* Wva = (const float*)d_in[12], *bva = (const float*)d_in[13];
    const float* Wkt = (const float*)d_in[14], *bkt = (const float*)d_in[15];
    const float* Wvt = (const float*)d_in[16], *bvt = (const float*)d_in[17];
    const float* Wo  = (const float*)d_in[18], *bo  = (const float*)d_in[19];
    const float* Wf  = (const float*)d_in[20], *bf  = (const float*)d_in[21];
    const float* gate = (const float*)d_in[22];
    const float* ln_g = (const float*)d_in[23];
    const float* ln_b = (const float*)d_in[24];

    float *Q, *Ks, *Vs, *Ka, *Va, *Kt, *Vt, *y;
    __half *Whi, *Wlo, *xh, *hadh, *hth, *ath, *ynh;
    cudaGetSymbolAddress((void**)&Q,    g_Q);
    cudaGetSymbolAddress((void**)&Ks,   g_Ks);
    cudaGetSymbolAddress((void**)&Vs,   g_Vs);
    cudaGetSymbolAddress((void**)&Ka,   g_Ka);
    cudaGetSymbolAddress((void**)&Va,   g_Va);
    cudaGetSymbolAddress((void**)&Kt,   g_Kt);
    cudaGetSymbolAddress((void**)&Vt,   g_Vt);
    cudaGetSymbolAddress((void**)&y,    g_y);
    cudaGetSymbolAddress((void**)&Whi,  g_Whi);
    cudaGetSymbolAddress((void**)&Wlo,  g_Wlo);
    cudaGetSymbolAddress((void**)&xh,   g_xh);
    cudaGetSymbolAddress((void**)&hadh, g_hadh);
    cudaGetSymbolAddress((void**)&hth,  g_hth);
    cudaGetSymbolAddress((void**)&ath,  g_ath);
    cudaGetSymbolAddress((void**)&ynh,  g_ynh);

    cudaFuncSetAttribute(wgemm_k, cudaFuncAttributeMaxDynamicSharedMemorySize, SM_TOTAL);

    rope_init_k<<<(512 * 112 + 255) / 256, 256>>>();

    WPtrs wp;
    wp.w[0] = Wq; wp.w[1] = Wks; wp.w[2] = Wvs; wp.w[3] = Wka; wp.w[4] = Wva;
    wp.w[5] = Wkt; wp.w[6] = Wvt; wp.w[7] = Wo; wp.w[8] = Wf;
    convw_k<<<dim3(28, 28, 9), dim3(32, 8)>>>(wp);

    cvt_k<<<(512 * 224 + 255) / 256, 256>>>(x, xh, 512 * 224);
    cvt_k<<<(32768 * 224 + 255) / 256, 256>>>(h_t, hth, 32768 * 224);
    build_had_k<<<(4224 * 224 + 255) / 256, 256>>>(h_a, p);

    const size_t WS = 896 * 896;

    // ---- one batched launch: Kt/Vt (3584) + Ka/Va (462) + QKV (84) --------
    {
        GB3 gb;
        gb.g[0].Ah = hth;
        gb.g[0].Bhi = Whi + 5 * WS; gb.g[0].Blo = Wlo + 5 * WS;
        gb.g[0].M = 32768; gb.g[0].ncol = 14;
        gb.g[0].out[0] = Kt; gb.g[0].bias[0] = bkt; gb.g[0].epi[0] = 1; gb.g[0].rl[0] = 512;
        gb.g[0].out[1] = Vt; gb.g[0].bias[1] = bvt; gb.g[0].epi[1] = 0; gb.g[0].rl[1] = 1;
        gb.g[0].out[2] = nullptr; gb.g[0].bias[2] = nullptr; gb.g[0].epi[2] = 0; gb.g[0].rl[2] = 1;
        gb.g[0].res = nullptr;

        gb.g[1].Ah = hadh;
        gb.g[1].Bhi = Whi + 3 * WS; gb.g[1].Blo = Wlo + 3 * WS;
        gb.g[1].M = 4160; gb.g[1].ncol = 14;
        gb.g[1].out[0] = Ka; gb.g[1].bias[0] = bka; gb.g[1].epi[0] = 1; gb.g[1].rl[0] = 65;
        gb.g[1].out[1] = Va; gb.g[1].bias[1] = bva; gb.g[1].epi[1] = 0; gb.g[1].rl[1] = 1;
        gb.g[1].out[2] = nullptr; gb.g[1].bias[2] = nullptr; gb.g[1].epi[2] = 0; gb.g[1].rl[2] = 1;
        gb.g[1].res = nullptr;

        gb.g[2].Ah = xh;
        gb.g[2].Bhi = Whi; gb.g[2].Blo = Wlo;
        gb.g[2].M = 512; gb.g[2].ncol = 21;
        gb.g[2].out[0] = Q;  gb.g[2].bias[0] = bq;  gb.g[2].epi[0] = 1; gb.g[2].rl[0] = 8;
        gb.g[2].out[1] = Ks; gb.g[2].bias[1] = bks; gb.g[2].epi[1] = 1; gb.g[2].rl[1] = 8;
        gb.g[2].out[2] = Vs; gb.g[2].bias[2] = bvs; gb.g[2].epi[2] = 0; gb.g[2].rl[2] = 1;
        gb.g[2].res = nullptr;
        gb.b0 = 3584; gb.b1 = 3584 + 462;
        wgemm_k<<<3584 + 462 + 84, 256, SM_TOTAL>>>(gb);
    }

    attn_k<<<512, 256>>>(gate);

    // ---- Wo: +bias +residual(x) -> y ---------------------------------------
    {
        GB3 gb;
        gb.g[0].Ah = ath;
        gb.g[0].Bhi = Whi + 7 * WS; gb.g[0].Blo = Wlo + 7 * WS;
        gb.g[0].M = 512; gb.g[0].ncol = 7;
        gb.g[0].out[0] = y; gb.g[0].bias[0] = bo; gb.g[0].epi[0] = 2; gb.g[0].rl[0] = 1;
        gb.g[0].out[1] = nullptr; gb.g[0].bias[1] = nullptr; gb.g[0].epi[1] = 0; gb.g[0].rl[1] = 1;
        gb.g[0].out[2] = nullptr; gb.g[0].bias[2] = nullptr; gb.g[0].epi[2] = 0; gb.g[0].rl[2] = 1;
        gb.g[0].res = x;
        gb.g[1] = gb.g[0]; gb.g[2] = gb.g[0];
        gb.b0 = 1 << 30; gb.b1 = 1 << 30;
        wgemm_k<<<28, 256, SM_TOTAL>>>(gb);
    }

    ln_k<<<512, 256>>>(ln_g, ln_b);

    // ---- Wf: +bias, ReLU -> d_out ------------------------------------------
    {
        GB3 gb;
        gb.g[0].Ah = ynh;
        gb.g[0].Bhi = Whi + 8 * WS; gb.g[0].Blo = Wlo + 8 * WS;
        gb.g[0].M = 512; gb.g[0].ncol = 7;
        gb.g[0].out[0] = (float*)d_out; gb.g[0].bias[0] = bf; gb.g[0].epi[0] = 3; gb.g[0].rl[0] = 1;
        gb.g[0].out[1] = nullptr; gb.g[0].bias[1] = nullptr; gb.g[0].epi[1] = 0; gb.g[0].rl[1] = 1;
        gb.g[0].out[2] = nullptr; gb.g[0].bias[2] = nullptr; gb.g[0].epi[2] = 0; gb.g[0].rl[2] = 1;
        gb.g[0].res = nullptr;
        gb.g[1] = gb.g[0]; gb.g[2] = gb.g[0];
        gb.b0 = 1 << 30; gb.b1 = 1 << 30;
        wgemm_k<<<28, 256, SM_TOTAL>>>(gb);
    }
}

// round 7
// speedup vs baseline: 5.0005x; 1.5549x over previous
#include <cuda_runtime.h>
#include <cuda_fp16.h>
#include <cstdint>

#define DIMN 896
#define NKEYS 585

// ==================== device scratch (no allocation) ========================
__device__ float  g_Q  [512   * 896];
__device__ __half g_Ks [512   * 896];
__device__ __half g_Vs [512   * 896];
__device__ __half g_Ka [4160  * 896];
__device__ __half g_Va [4160  * 896];
__device__ __half g_Kt [32768 * 896];
__device__ __half g_Vt [32768 * 896];
__device__ float  g_y  [512   * 896];
__device__ float2 g_rope[512 * 112];
__device__ __half g_W  [9][896 * 896];   // W^T fp16 [n][k]
__device__ __half g_xh  [512   * 896];
__device__ __half g_hadh[4224  * 896];
__device__ __half g_hth [32768 * 896];
__device__ __half g_ath [512   * 896];
__device__ __half g_ynh [512   * 896];

// ==================== helpers ===============================================
__device__ __forceinline__ uint32_t smem_u32(const void* p) {
    uint32_t a;
    asm("{ .reg .u64 t; cvta.to.shared.u64 t, %1; cvt.u32.u64 %0, t; }" : "=r"(a) : "l"(p));
    return a;
}
#define CP_ASYNC16(dst, src) asm volatile("cp.async.cg.shared.global [%0], [%1], 16;" :: "r"(dst), "l"(src))
#define CP_COMMIT()          asm volatile("cp.async.commit_group;" ::: "memory")
#define CP_WAIT1()           asm volatile("cp.async.wait_group 1;" ::: "memory")

#define LDSM4(r0, r1, r2, r3, addr) \
    asm volatile("ldmatrix.sync.aligned.m8n8.x4.shared.b16 {%0,%1,%2,%3}, [%4];" \
        : "=r"(r0), "=r"(r1), "=r"(r2), "=r"(r3) : "r"(addr))

#define MMA_F16(d, a, b0, b1) \
    asm volatile("mma.sync.aligned.m16n8k16.row.col.f32.f16.f16.f32 " \
        "{%0,%1,%2,%3}, {%4,%5,%6,%7}, {%8,%9}, {%0,%1,%2,%3};" \
        : "+f"((d)[0]), "+f"((d)[1]), "+f"((d)[2]), "+f"((d)[3]) \
        : "r"((a)[0]), "r"((a)[1]), "r"((a)[2]), "r"((a)[3]), "r"(b0), "r"(b1))

__device__ __forceinline__ uint2 cvt4h(float4 v) {
    __half2 lo = __floats2half2_rn(v.x, v.y);
    __half2 hi = __floats2half2_rn(v.z, v.w);
    return make_uint2(*(uint32_t*)&lo, *(uint32_t*)&hi);
}

// ==================== small prep kernels ====================================
__global__ void rope_init_k() {
    int i = blockIdx.x * blockDim.x + threadIdx.x;
    if (i >= 512 * 112) return;
    int pos = i / 112, d = i % 112, f = d % 56;
    float inv = powf(10000.0f, -((float)(2 * f) / 112.0f));
    float ang = (float)pos * inv;
    g_rope[i] = make_float2(cosf(ang), sinf(ang));
}

__global__ void cvt_k(const float* __restrict__ src, __half* __restrict__ dst, int n4)
{
    int i = blockIdx.x * blockDim.x + threadIdx.x;
    if (i >= n4) return;
    ((uint2*)dst)[i] = cvt4h(((const float4*)src)[i]);
}

__global__ void build_had_k(const float* __restrict__ h_a, const float* __restrict__ p) {
    int i = blockIdx.x * blockDim.x + threadIdx.x;
    if (i >= 4224 * 224) return;
    int row = i / 224, c4 = i % 224;
    float4 v = make_float4(0.f, 0.f, 0.f, 0.f);
    if (row < 4160) {
        int b = row / 65, l = row % 65;
        v = (l < 64) ? ((const float4*)(h_a + ((size_t)(b * 64 + l)) * 896))[c4]
                     : ((const float4*)(p   + (size_t)b * 896))[c4];
    }
    ((uint2*)g_hadh)[i] = cvt4h(v);
}

struct WPtrs { const float* w[9]; };
// transpose + fp16 round of all 9 weights: W[k][n] -> W^T[n][k]
__global__ void convw_k(WPtrs wp) {
    __shared__ float tile[32][33];
    int wi = blockIdx.z;
    const float* W = wp.w[wi];
    __half* dst = g_W[wi];
    int tx = threadIdx.x, ty = threadIdx.y;
    int k0 = blockIdx.y * 32, n0 = blockIdx.x * 32;
    #pragma unroll
    for (int i = 0; i < 4; i++)
        tile[ty + i * 8][tx] = W[(size_t)(k0 + ty + i * 8) * 896 + n0 + tx];
    __syncthreads();
    #pragma unroll
    for (int i = 0; i < 4; i++) {
        int n = n0 + ty + i * 8, k = k0 + tx;
        dst[(size_t)n * 896 + k] = __float2half_rn(tile[tx][ty + i * 8]);
    }
}

// ==================== batched single-pass fp16 GEMM =========================
// CTA tile 128x128x32, 8 warps (4Mx2N), 3-stage cp.async pipeline, occ 2.
// stage layout (bytes): A 0, B 10240; stage=20480
#define LDAB 80
#define STAGE_B 20480
#define SM_TOTAL (3 * STAGE_B)

struct GB {
    const __half *Ah, *B;
    int M, ncol;
    void* out[3];
    const float* bias[3];
    int epi[3];      // 0 bias; 1 bias+RoPE; 2 bias+res; 3 bias+ReLU
    int rl[3];
    int hout[3];     // 1 = fp16 output
    const float* res;
};
struct GB3 { GB g[3]; int b0, b1; };

__device__ __forceinline__ void stage_load(
    uint32_t s0, const __half* __restrict__ Ah, const __half* __restrict__ B,
    int row0, int col0, int kt, int tid)
{
    #pragma unroll
    for (int i = 0; i < 4; i++) {
        const int sel = i >> 1;
        int cc = (i & 1) * 256 + tid;
        int r = cc >> 2, ks = cc & 3;
        const __half* base = sel ? B : Ah;
        int rowg = sel ? (col0 + r) : (row0 + r);
        uint32_t dst = s0 + (uint32_t)sel * 10240u + (uint32_t)(r * LDAB + ks * 16);
        CP_ASYNC16(dst, base + (size_t)rowg * 896 + kt + ks * 8);
    }
}

__global__ __launch_bounds__(256, 2) void wgemm_k(GB3 gb)
{
    extern __shared__ __align__(128) char smx[];
    const int id = blockIdx.x;
    const int gi = (id < gb.b0) ? 0 : (id < gb.b1) ? 1 : 2;
    const int local = id - ((gi == 0) ? 0 : (gi == 1) ? gb.b0 : gb.b1);
    const GB& G = gb.g[gi];
    const int colTile = local % G.ncol;
    const int row0 = (local / G.ncol) * 128;
    const int col0 = colTile * 128;

    const int tid  = threadIdx.x;
    const int lane = tid & 31, wid = tid >> 5;
    const int wm = (wid & 3) * 32, wn = (wid >> 2) * 64;
    uint32_t sb = smem_u32(smx);

    float acc[2][8][4];
    #pragma unroll
    for (int mi = 0; mi < 2; mi++)
        #pragma unroll
        for (int nj = 0; nj < 8; nj++)
            #pragma unroll
            for (int q = 0; q < 4; q++) acc[mi][nj][q] = 0.0f;

    const int a_r = lane & 15;
    const int a_k = (lane >> 4) * 16;
    const int b_r = (lane & 7) + ((lane >> 4) & 1) * 8;
    const int b_k = ((lane >> 3) & 1) * 16;

    stage_load(sb, G.Ah, G.B, row0, col0, 0, tid);
    CP_COMMIT();
    stage_load(sb + STAGE_B, G.Ah, G.B, row0, col0, 32, tid);
    CP_COMMIT();

    #pragma unroll 1
    for (int t = 0; t < 28; t++) {
        CP_WAIT1();
        __syncthreads();          // stage t ready; all warps done with stage t-1
        if (t + 2 < 28)
            stage_load(sb + ((t + 2) % 3) * STAGE_B, G.Ah, G.B, row0, col0, (t + 2) * 32, tid);
        CP_COMMIT();

        uint32_t s0 = sb + (t % 3) * STAGE_B;
        uint32_t aB = s0 +         (uint32_t)((wm + a_r) * LDAB + a_k);
        uint32_t bB = s0 + 10240 + (uint32_t)((wn + b_r) * LDAB + b_k);
        #pragma unroll
        for (int ks = 0; ks < 2; ks++) {
            const uint32_t ksb = ks * 32;
            uint32_t a[2][4], bh[8][2];
            #pragma unroll
            for (int mi = 0; mi < 2; mi++)
                LDSM4(a[mi][0], a[mi][1], a[mi][2], a[mi][3], aB + mi * (16 * LDAB) + ksb);
            #pragma unroll
            for (int p = 0; p < 4; p++)
                LDSM4(bh[2*p][0], bh[2*p][1], bh[2*p+1][0], bh[2*p+1][1], bB + p * (16 * LDAB) + ksb);
            #pragma unroll
            for (int mi = 0; mi < 2; mi++)
                #pragma unroll
                for (int nj = 0; nj < 8; nj++)
                    MMA_F16(acc[mi][nj], a[mi], bh[nj][0], bh[nj][1]);
        }
    }

    // ---------------- epilogue ----------------
    const int cb = colTile / 7;
    const int lcol0 = (colTile % 7) * 128;
    const float* bias = G.bias[cb];
    const int epi = G.epi[cb];
    const int ropeL = G.rl[cb];
    const int hout = G.hout[cb];

    #pragma unroll
    for (int mi = 0; mi < 2; mi++) {
        #pragma unroll
        for (int half = 0; half < 2; half++) {
            int row = row0 + wm + mi * 16 + (lane >> 2) + half * 8;
            if (row >= G.M) continue;
            const float2* rt = (epi == 1) ? (g_rope + (size_t)(row % ropeL) * 112) : nullptr;
            const float* rrow = (epi == 2) ? (G.res + (size_t)row * DIMN) : nullptr;
            float* crowf = (float*)G.out[cb] + (size_t)row * DIMN;
            __half* crowh = (__half*)G.out[cb] + (size_t)row * DIMN;
            #pragma unroll
            for (int nj = 0; nj < 8; nj++) {
                int gc = lcol0 + wn + nj * 8 + (lane & 3) * 2;
                float v0 = acc[mi][nj][half * 2]     + bias[gc];
                float v1 = acc[mi][nj][half * 2 + 1] + bias[gc + 1];
                float2 o;
                if (epi == 1) {
                    int d = gc % 112;
                    float2 r0 = rt[d], r1 = rt[d + 1];
                    o.x = v0 * r0.x - v1 * r0.y;
                    o.y = v1 * r1.x + v0 * r1.y;
                } else if (epi == 2) {
                    o.x = v0 + rrow[gc]; o.y = v1 + rrow[gc + 1];
                } else if (epi == 3) {
                    o.x = fmaxf(v0, 0.f); o.y = fmaxf(v1, 0.f);
                } else {
                    o.x = v0; o.y = v1;
                }
                if (hout) {
                    __half2 h2 = __floats2half2_rn(o.x, o.y);
                    *(uint32_t*)(crowh + gc) = *(uint32_t*)&h2;
                } else {
                    *(float2*)(crowf + gc) = o;
                }
            }
        }
    }
}

// ==================== attention (fp16 K/V, emits fp16) ======================
__global__ __launch_bounds__(256) void attn_k(const float* __restrict__ gate)
{
    const int b = blockIdx.x >> 3, h = blockIdx.x & 7;
    __shared__ float q_s[8][112];
    __shared__ float w_s[8][592];
    __shared__ const __half* kp[NKEYS];
    __shared__ const __half* vp[NKEYS];
    const int tid = threadIdx.x;

    for (int i = tid; i < 8 * 112; i += 256) {
        int r = i / 112, d = i % 112;
        q_s[r][d] = g_Q[((size_t)(b * 8 + r)) * 896 + h * 112 + d];
    }
    for (int k = tid; k < NKEYS; k += 256) {
        size_t o;
        const __half *kb, *vb;
        if (k < 8)       { o = ((size_t)(b * 8 + k)) * 896 + h * 112;          kb = g_Ks + o; vb = g_Vs + o; }
        else if (k < 73) { o = ((size_t)(b * 65 + (k - 8))) * 896 + h * 112;   kb = g_Ka + o; vb = g_Va + o; }
        else             { o = ((size_t)(b * 512 + (k - 73))) * 896 + h * 112; kb = g_Kt + o; vb = g_Vt + o; }
        kp[k] = kb; vp[k] = vb;
    }
    __syncthreads();

    const float ratio = tanhf(gate[0]);
    const float sc0   = rsqrtf(112.0f);

    for (int k = tid; k < NKEYS; k += 256) {
        const __half* kb = kp[k];
        float acc[8] = {0.f, 0.f, 0.f, 0.f, 0.f, 0.f, 0.f, 0.f};
        #pragma unroll 2
        for (int d8 = 0; d8 < 14; ++d8) {
            uint4 raw = *(const uint4*)(kb + d8 * 8);
            const __half2* hp = (const __half2*)&raw;
            float2 f0 = __half22float2(hp[0]);
            float2 f1 = __half22float2(hp[1]);
            float2 f2 = __half22float2(hp[2]);
            float2 f3 = __half22float2(hp[3]);
            #pragma unroll
            for (int r = 0; r < 8; r++) {
                const float* q = &q_s[r][d8 * 8];
                acc[r] = fmaf(q[0], f0.x, acc[r]);
                acc[r] = fmaf(q[1], f0.y, acc[r]);
                acc[r] = fmaf(q[2], f1.x, acc[r]);
                acc[r] = fmaf(q[3], f1.y, acc[r]);
                acc[r] = fmaf(q[4], f2.x, acc[r]);
                acc[r] = fmaf(q[5], f2.y, acc[r]);
                acc[r] = fmaf(q[6], f3.x, acc[r]);
                acc[r] = fmaf(q[7], f3.y, acc[r]);
            }
        }
        float sc = (k < 73) ? sc0 : sc0 * ratio;
        #pragma unroll
        for (int r = 0; r < 8; r++) w_s[r][k] = acc[r] * sc;
    }
    __syncthreads();

    {
        int r = tid >> 5, lane = tid & 31;
        float m = -3.0e38f;
        for (int k = lane; k < NKEYS; k += 32) m = fmaxf(m, w_s[r][k]);
        #pragma unroll
        for (int o = 16; o; o >>= 1) m = fmaxf(m, __shfl_xor_sync(0xffffffffu, m, o));
        float s = 0.0f;
        for (int k = lane; k < NKEYS; k += 32) { float e = __expf(w_s[r][k] - m); w_s[r][k] = e; s += e; }
        #pragma unroll
        for (int o = 16; o; o >>= 1) s += __shfl_xor_sync(0xffffffffu, s, o);
        float inv = 1.0f / s;
        for (int k = lane; k < NKEYS; k += 32) w_s[r][k] *= inv;
    }
    __syncthreads();

    for (int idx = tid; idx < 896; idx += 256) {
        int r = idx / 112, d = idx % 112;
        float acc = 0.0f;
        #pragma unroll 4
        for (int k = 0; k < NKEYS; k++) acc = fmaf(w_s[r][k], __half2float(vp[k][d]), acc);
        g_ath[((size_t)(b * 8 + r)) * 896 + h * 112 + d] = __float2half_rn(acc);
    }
}

// ==================== layernorm (emits fp16) ================================
__global__ __launch_bounds__(256) void ln_k(const float* __restrict__ g,
                                            const float* __restrict__ bt)
{
    int row = blockIdx.x;
    const float* y = g_y + (size_t)row * 896;
    int tid = threadIdx.x;
    float s = 0.0f, s2 = 0.0f;
    for (int j = tid; j < 896; j += 256) { float v = y[j]; s += v; s2 += v * v; }
    __shared__ float rs[8], rs2[8];
    #pragma unroll
    for (int o = 16; o; o >>= 1) { s += __shfl_xor_sync(~0u, s, o); s2 += __shfl_xor_sync(~0u, s2, o); }
    if ((tid & 31) == 0) { rs[tid >> 5] = s; rs2[tid >> 5] = s2; }
    __syncthreads();
    if (tid < 32) {
        s  = (tid < 8) ? rs[tid]  : 0.0f;
        s2 = (tid < 8) ? rs2[tid] : 0.0f;
        #pragma unroll
        for (int o = 4; o; o >>= 1) { s += __shfl_xor_sync(~0u, s, o); s2 += __shfl_xor_sync(~0u, s2, o); }
        if (tid == 0) { rs[0] = s; rs2[0] = s2; }
    }
    __syncthreads();
    float mu  = rs[0]  * (1.0f / 896.0f);
    float var = rs2[0] * (1.0f / 896.0f) - mu * mu;
    float inv = rsqrtf(var + 1e-5f);
    for (int j = tid; j < 896; j += 256)
        g_ynh[(size_t)row * 896 + j] = __float2half_rn((y[j] - mu) * inv * g[j] + bt[j]);
}

// ==================== host orchestration ====================================
extern "C" void kernel_launch(void* const* d_in, const int* in_sizes, int n_in,
                              void* d_out, int out_size)
{
    const float* x   = (const float*)d_in[0];
    const float* h_a = (const float*)d_in[1];
    const float* h_t = (const float*)d_in[2];
    const float* p   = (const float*)d_in[3];
    const float* Wq  = (const float*)d_in[4],  *bq  = (const float*)d_in[5];
    const float* Wks = (const float*)d_in[6],  *bks = (const float*)d_in[7];
    const float* Wvs = (const float*)d_in[8],  *bvs = (const float*)d_in[9];
    const float* Wka = (const float*)d_in[10], *bka = (const float*)d_in[11];
    const float* Wva = (const float*)d_in[12], *bva = (const float*)d_in[13];
    const float* Wkt = (const float*)d_in[14], *bkt = (const float*)d_in[15];
    const float* Wvt = (const float*)d_in[16], *bvt = (const float*)d_in[17];
    const float* Wo  = (const float*)d_in[18], *bo  = (const float*)d_in[19];
    const float* Wf  = (const float*)d_in[20], *bf  = (const float*)d_in[21];
    const float* gate = (const float*)d_in[22];
    const float* ln_g = (const float*)d_in[23];
    const float* ln_b = (const float*)d_in[24];

    float *Q, *y;
    __half *Ks, *Vs, *Ka, *Va, *Kt, *Vt;
    __half *W, *xh, *hadh, *hth, *ath, *ynh;
    cudaGetSymbolAddress((void**)&Q,    g_Q);
    cudaGetSymbolAddress((void**)&Ks,   g_Ks);
    cudaGetSymbolAddress((void**)&Vs,   g_Vs);
    cudaGetSymbolAddress((void**)&Ka,   g_Ka);
    cudaGetSymbolAddress((void**)&Va,   g_Va);
    cudaGetSymbolAddress((void**)&Kt,   g_Kt);
    cudaGetSymbolAddress((void**)&Vt,   g_Vt);
    cudaGetSymbolAddress((void**)&y,    g_y);
    cudaGetSymbolAddress((void**)&W,    g_W);
    cudaGetSymbolAddress((void**)&xh,   g_xh);
    cudaGetSymbolAddress((void**)&hadh, g_hadh);
    cudaGetSymbolAddress((void**)&hth,  g_hth);
    cudaGetSymbolAddress((void**)&ath,  g_ath);
    cudaGetSymbolAddress((void**)&ynh,  g_ynh);

    cudaFuncSetAttribute(wgemm_k, cudaFuncAttributeMaxDynamicSharedMemorySize, SM_TOTAL);

    rope_init_k<<<(512 * 112 + 255) / 256, 256>>>();

    WPtrs wp;
    wp.w[0] = Wq; wp.w[1] = Wks; wp.w[2] = Wvs; wp.w[3] = Wka; wp.w[4] = Wva;
    wp.w[5] = Wkt; wp.w[6] = Wvt; wp.w[7] = Wo; wp.w[8] = Wf;
    convw_k<<<dim3(28, 28, 9), dim3(32, 8)>>>(wp);

    cvt_k<<<(512 * 224 + 255) / 256, 256>>>(x, xh, 512 * 224);
    cvt_k<<<(32768 * 224 + 255) / 256, 256>>>(h_t, hth, 32768 * 224);
    build_had_k<<<(4224 * 224 + 255) / 256, 256>>>(h_a, p);

    const size_t WS = 896 * 896;

    // ---- one batched launch: Kt/Vt (3584) + Ka/Va (462) + QKV (84) --------
    {
        GB3 gb;
        gb.g[0].Ah = hth; gb.g[0].B = W + 5 * WS;
        gb.g[0].M = 32768; gb.g[0].ncol = 14;
        gb.g[0].out[0] = Kt; gb.g[0].bias[0] = bkt; gb.g[0].epi[0] = 1; gb.g[0].rl[0] = 512; gb.g[0].hout[0] = 1;
        gb.g[0].out[1] = Vt; gb.g[0].bias[1] = bvt; gb.g[0].epi[1] = 0; gb.g[0].rl[1] = 1;   gb.g[0].hout[1] = 1;
        gb.g[0].out[2] = nullptr; gb.g[0].bias[2] = nullptr; gb.g[0].epi[2] = 0; gb.g[0].rl[2] = 1; gb.g[0].hout[2] = 0;
        gb.g[0].res = nullptr;

        gb.g[1].Ah = hadh; gb.g[1].B = W + 3 * WS;
        gb.g[1].M = 4160; gb.g[1].ncol = 14;
        gb.g[1].out[0] = Ka; gb.g[1].bias[0] = bka; gb.g[1].epi[0] = 1; gb.g[1].rl[0] = 65; gb.g[1].hout[0] = 1;
        gb.g[1].out[1] = Va; gb.g[1].bias[1] = bva; gb.g[1].epi[1] = 0; gb.g[1].rl[1] = 1;  gb.g[1].hout[1] = 1;
        gb.g[1].out[2] = nullptr; gb.g[1].bias[2] = nullptr; gb.g[1].epi[2] = 0; gb.g[1].rl[2] = 1; gb.g[1].hout[2] = 0;
        gb.g[1].res = nullptr;

        gb.g[2].Ah = xh; gb.g[2].B = W;
        gb.g[2].M = 512; gb.g[2].ncol = 21;
        gb.g[2].out[0] = Q;  gb.g[2].bias[0] = bq;  gb.g[2].epi[0] = 1; gb.g[2].rl[0] = 8; gb.g[2].hout[0] = 0;
        gb.g[2].out[1] = Ks; gb.g[2].bias[1] = bks; gb.g[2].epi[1] = 1; gb.g[2].rl[1] = 8; gb.g[2].hout[1] = 1;
        gb.g[2].out[2] = Vs; gb.g[2].bias[2] = bvs; gb.g[2].epi[2] = 0; gb.g[2].rl[2] = 1; gb.g[2].hout[2] = 1;
        gb.g[2].res = nullptr;
        gb.b0 = 3584; gb.b1 = 3584 + 462;
        wgemm_k<<<3584 + 462 + 84, 256, SM_TOTAL>>>(gb);
    }

    attn_k<<<512, 256>>>(gate);

    // ---- Wo: +bias +residual(x) -> y ---------------------------------------
    {
        GB3 gb;
        gb.g[0].Ah = ath; gb.g[0].B = W + 7 * WS;
        gb.g[0].M = 512; gb.g[0].ncol = 7;
        gb.g[0].out[0] = y; gb.g[0].bias[0] = bo; gb.g[0].epi[0] = 2; gb.g[0].rl[0] = 1; gb.g[0].hout[0] = 0;
        gb.g[0].out[1] = nullptr; gb.g[0].bias[1] = nullptr; gb.g[0].epi[1] = 0; gb.g[0].rl[1] = 1; gb.g[0].hout[1] = 0;
        gb.g[0].out[2] = nullptr; gb.g[0].bias[2] = nullptr; gb.g[0].epi[2] = 0; gb.g[0].rl[2] = 1; gb.g[0].hout[2] = 0;
        gb.g[0].res = x;
        gb.g[1] = gb.g[0]; gb.g[2] = gb.g[0];
        gb.b0 = 1 << 30; gb.b1 = 1 << 30;
        wgemm_k<<<28, 256, SM_TOTAL>>>(gb);
    }

    ln_k<<<512, 256>>>(ln_g, ln_b);

    // ---- Wf: +bias, ReLU -> d_out ------------------------------------------
    {
        GB3 gb;
        gb.g[0].Ah = ynh; gb.g[0].B = W + 8 * WS;
        gb.g[0].M = 512; gb.g[0].ncol = 7;
        gb.g[0].out[0] = d_out; gb.g[0].bias[0] = bf; gb.g[0].epi[0] = 3; gb.g[0].rl[0] = 1; gb.g[0].hout[0] = 0;
        gb.g[0].out[1] = nullptr; gb.g[0].bias[1] = nullptr; gb.g[0].epi[1] = 0; gb.g[0].rl[1] = 1; gb.g[0].hout[1] = 0;
        gb.g[0].out[2] = nullptr; gb.g[0].bias[2] = nullptr; gb.g[0].epi[2] = 0; gb.g[0].rl[2] = 1; gb.g[0].hout[2] = 0;
        gb.g[0].res = nullptr;
        gb.g[1] = gb.g[0]; gb.g[2] = gb.g[0];
        gb.b0 = 1 << 30; gb.b1 = 1 << 30;
        wgemm_k<<<28, 256, SM_TOTAL>>>(gb);
    }
}

// round 8
// speedup vs baseline: 7.4700x; 1.4938x over previous
#include <cuda_runtime.h>
#include <cuda_fp16.h>
#include <cstdint>

#define DIMN 896
#define NKEYS 585

// ==================== device scratch (no allocation) ========================
__device__ float  g_Q  [512   * 896];
__device__ __half g_Ks [512   * 896];
__device__ __half g_Vs [512   * 896];
__device__ __half g_Ka [4160  * 896];
__device__ __half g_Va [4160  * 896];
__device__ __half g_Kt [32768 * 896];
__device__ float  g_y  [512   * 896];
__device__ float2 g_rope[512 * 112];
__device__ __half g_W  [9][896 * 896];   // W^T fp16 [n][k]
__device__ __half g_xh  [512   * 896];
__device__ __half g_hadh[4224  * 896];
__device__ __half g_hth [32768 * 896];
__device__ __half g_ath [512   * 896];
__device__ __half g_ynh [512   * 896];
// attention factorization buffers
__device__ __half g_wt   [64 * 64 * 512];   // task weights, [b][(h*8+t)][512]
__device__ float  g_st   [4096];            // task weight sums, [(b*8+h)*8+t]
__device__ float  g_oPart[4096 * 112];      // self+ad AV partial, [(b*8+h)*8+t][112]
__device__ __half g_wsum [4096 * 896];      // [(b*64 + h*8 + t)][896]

// ==================== helpers ===============================================
__device__ __forceinline__ uint32_t smem_u32(const void* p) {
    uint32_t a;
    asm("{ .reg .u64 t; cvta.to.shared.u64 t, %1; cvt.u32.u64 %0, t; }" : "=r"(a) : "l"(p));
    return a;
}
#define CP_ASYNC16(dst, src) asm volatile("cp.async.cg.shared.global [%0], [%1], 16;" :: "r"(dst), "l"(src))
#define CP_COMMIT()          asm volatile("cp.async.commit_group;" ::: "memory")
#define CP_WAIT0()           asm volatile("cp.async.wait_group 0;" ::: "memory")
#define CP_WAIT1()           asm volatile("cp.async.wait_group 1;" ::: "memory")

#define LDSM4(r0, r1, r2, r3, addr) \
    asm volatile("ldmatrix.sync.aligned.m8n8.x4.shared.b16 {%0,%1,%2,%3}, [%4];" \
        : "=r"(r0), "=r"(r1), "=r"(r2), "=r"(r3) : "r"(addr))

#define LDSM4_T(r0, r1, r2, r3, addr) \
    asm volatile("ldmatrix.sync.aligned.m8n8.x4.trans.shared.b16 {%0,%1,%2,%3}, [%4];" \
        : "=r"(r0), "=r"(r1), "=r"(r2), "=r"(r3) : "r"(addr))

#define MMA_F16(d, a, b0, b1) \
    asm volatile("mma.sync.aligned.m16n8k16.row.col.f32.f16.f16.f32 " \
        "{%0,%1,%2,%3}, {%4,%5,%6,%7}, {%8,%9}, {%0,%1,%2,%3};" \
        : "+f"((d)[0]), "+f"((d)[1]), "+f"((d)[2]), "+f"((d)[3]) \
        : "r"((a)[0]), "r"((a)[1]), "r"((a)[2]), "r"((a)[3]), "r"(b0), "r"(b1))

__device__ __forceinline__ uint2 cvt4h(float4 v) {
    __half2 lo = __floats2half2_rn(v.x, v.y);
    __half2 hi = __floats2half2_rn(v.z, v.w);
    return make_uint2(*(uint32_t*)&lo, *(uint32_t*)&hi);
}

// ==================== small prep kernels ====================================
__global__ void rope_init_k() {
    int i = blockIdx.x * blockDim.x + threadIdx.x;
    if (i >= 512 * 112) return;
    int pos = i / 112, d = i % 112, f = d % 56;
    float inv = powf(10000.0f, -((float)(2 * f) / 112.0f));
    float ang = (float)pos * inv;
    g_rope[i] = make_float2(cosf(ang), sinf(ang));
}

__global__ void cvt_k(const float* __restrict__ src, __half* __restrict__ dst, int n4)
{
    int i = blockIdx.x * blockDim.x + threadIdx.x;
    if (i >= n4) return;
    ((uint2*)dst)[i] = cvt4h(((const float4*)src)[i]);
}

__global__ void build_had_k(const float* __restrict__ h_a, const float* __restrict__ p) {
    int i = blockIdx.x * blockDim.x + threadIdx.x;
    if (i >= 4224 * 224) return;
    int row = i / 224, c4 = i % 224;
    float4 v = make_float4(0.f, 0.f, 0.f, 0.f);
    if (row < 4160) {
        int b = row / 65, l = row % 65;
        v = (l < 64) ? ((const float4*)(h_a + ((size_t)(b * 64 + l)) * 896))[c4]
                     : ((const float4*)(p   + (size_t)b * 896))[c4];
    }
    ((uint2*)g_hadh)[i] = cvt4h(v);
}

struct WPtrs { const float* w[9]; };
__global__ void convw_k(WPtrs wp) {
    __shared__ float tile[32][33];
    int wi = blockIdx.z;
    const float* W = wp.w[wi];
    __half* dst = g_W[wi];
    int tx = threadIdx.x, ty = threadIdx.y;
    int k0 = blockIdx.y * 32, n0 = blockIdx.x * 32;
    #pragma unroll
    for (int i = 0; i < 4; i++)
        tile[ty + i * 8][tx] = W[(size_t)(k0 + ty + i * 8) * 896 + n0 + tx];
    __syncthreads();
    #pragma unroll
    for (int i = 0; i < 4; i++) {
        int n = n0 + ty + i * 8, k = k0 + tx;
        dst[(size_t)n * 896 + k] = __float2half_rn(tile[tx][ty + i * 8]);
    }
}

// ==================== batched single-pass fp16 GEMM =========================
#define LDAB 80
#define STAGE_B 20480
#define SM_TOTAL (3 * STAGE_B)

struct GB {
    const __half *Ah, *B;
    int M, ncol;
    void* out[3];
    const float* bias[3];
    int epi[3];      // 0 bias; 1 bias+RoPE; 2 bias+res; 3 bias+ReLU
    int rl[3];
    int hout[3];
    const float* res;
};
struct GB3 { GB g[3]; int b0, b1; };

__device__ __forceinline__ void stage_load(
    uint32_t s0, const __half* __restrict__ Ah, const __half* __restrict__ B,
    int row0, int col0, int kt, int tid)
{
    #pragma unroll
    for (int i = 0; i < 4; i++) {
        const int sel = i >> 1;
        int cc = (i & 1) * 256 + tid;
        int r = cc >> 2, ks = cc & 3;
        const __half* base = sel ? B : Ah;
        int rowg = sel ? (col0 + r) : (row0 + r);
        uint32_t dst = s0 + (uint32_t)sel * 10240u + (uint32_t)(r * LDAB + ks * 16);
        CP_ASYNC16(dst, base + (size_t)rowg * 896 + kt + ks * 8);
    }
}

__global__ __launch_bounds__(256, 2) void wgemm_k(GB3 gb)
{
    extern __shared__ __align__(128) char smx[];
    const int id = blockIdx.x;
    const int gi = (id < gb.b0) ? 0 : (id < gb.b1) ? 1 : 2;
    const int local = id - ((gi == 0) ? 0 : (gi == 1) ? gb.b0 : gb.b1);
    const GB& G = gb.g[gi];
    const int colTile = local % G.ncol;
    const int row0 = (local / G.ncol) * 128;
    const int col0 = colTile * 128;

    const int tid  = threadIdx.x;
    const int lane = tid & 31, wid = tid >> 5;
    const int wm = (wid & 3) * 32, wn = (wid >> 2) * 64;
    uint32_t sb = smem_u32(smx);

    float acc[2][8][4];
    #pragma unroll
    for (int mi = 0; mi < 2; mi++)
        #pragma unroll
        for (int nj = 0; nj < 8; nj++)
            #pragma unroll
            for (int q = 0; q < 4; q++) acc[mi][nj][q] = 0.0f;

    const int a_r = lane & 15;
    const int a_k = (lane >> 4) * 16;
    const int b_r = (lane & 7) + ((lane >> 4) & 1) * 8;
    const int b_k = ((lane >> 3) & 1) * 16;

    stage_load(sb, G.Ah, G.B, row0, col0, 0, tid);
    CP_COMMIT();
    stage_load(sb + STAGE_B, G.Ah, G.B, row0, col0, 32, tid);
    CP_COMMIT();

    #pragma unroll 1
    for (int t = 0; t < 28; t++) {
        CP_WAIT1();
        __syncthreads();
        if (t + 2 < 28)
            stage_load(sb + ((t + 2) % 3) * STAGE_B, G.Ah, G.B, row0, col0, (t + 2) * 32, tid);
        CP_COMMIT();

        uint32_t s0 = sb + (t % 3) * STAGE_B;
        uint32_t aB = s0 +         (uint32_t)((wm + a_r) * LDAB + a_k);
        uint32_t bB = s0 + 10240 + (uint32_t)((wn + b_r) * LDAB + b_k);
        #pragma unroll
        for (int ks = 0; ks < 2; ks++) {
            const uint32_t ksb = ks * 32;
            uint32_t a[2][4], bh[8][2];
            #pragma unroll
            for (int mi = 0; mi < 2; mi++)
                LDSM4(a[mi][0], a[mi][1], a[mi][2], a[mi][3], aB + mi * (16 * LDAB) + ksb);
            #pragma unroll
            for (int p = 0; p < 4; p++)
                LDSM4(bh[2*p][0], bh[2*p][1], bh[2*p+1][0], bh[2*p+1][1], bB + p * (16 * LDAB) + ksb);
            #pragma unroll
            for (int mi = 0; mi < 2; mi++)
                #pragma unroll
                for (int nj = 0; nj < 8; nj++)
                    MMA_F16(acc[mi][nj], a[mi], bh[nj][0], bh[nj][1]);
        }
    }

    const int cb = colTile / 7;
    const int lcol0 = (colTile % 7) * 128;
    const float* bias = G.bias[cb];
    const int epi = G.epi[cb];
    const int ropeL = G.rl[cb];
    const int hout = G.hout[cb];

    #pragma unroll
    for (int mi = 0; mi < 2; mi++) {
        #pragma unroll
        for (int half = 0; half < 2; half++) {
            int row = row0 + wm + mi * 16 + (lane >> 2) + half * 8;
            if (row >= G.M) continue;
            const float2* rt = (epi == 1) ? (g_rope + (size_t)(row % ropeL) * 112) : nullptr;
            const float* rrow = (epi == 2) ? (G.res + (size_t)row * DIMN) : nullptr;
            float* crowf = (float*)G.out[cb] + (size_t)row * DIMN;
            __half* crowh = (__half*)G.out[cb] + (size_t)row * DIMN;
            #pragma unroll
            for (int nj = 0; nj < 8; nj++) {
                int gc = lcol0 + wn + nj * 8 + (lane & 3) * 2;
                float v0 = acc[mi][nj][half * 2]     + bias[gc];
                float v1 = acc[mi][nj][half * 2 + 1] + bias[gc + 1];
                float2 o;
                if (epi == 1) {
                    int d = gc % 112;
                    float2 r0 = rt[d], r1 = rt[d + 1];
                    o.x = v0 * r0.x - v1 * r0.y;
                    o.y = v1 * r1.x + v0 * r1.y;
                } else if (epi == 2) {
                    o.x = v0 + rrow[gc]; o.y = v1 + rrow[gc + 1];
                } else if (epi == 3) {
                    o.x = fmaxf(v0, 0.f); o.y = fmaxf(v1, 0.f);
                } else {
                    o.x = v0; o.y = v1;
                }
                if (hout) {
                    __half2 h2 = __floats2half2_rn(o.x, o.y);
                    *(uint32_t*)(crowh + gc) = *(uint32_t*)&h2;
                } else {
                    *(float2*)(crowf + gc) = o;
                }
            }
        }
    }
}

// ==================== attention (scores + softmax + self/ad AV) =============
__global__ __launch_bounds__(256) void attn_k(const float* __restrict__ gate)
{
    const int b = blockIdx.x >> 3, h = blockIdx.x & 7;
    __shared__ float q_s[8][112];
    __shared__ float w_s[8][592];
    __shared__ const __half* kp[NKEYS];
    __shared__ const __half* vp[73];
    const int tid = threadIdx.x;

    for (int i = tid; i < 8 * 112; i += 256) {
        int r = i / 112, d = i % 112;
        q_s[r][d] = g_Q[((size_t)(b * 8 + r)) * 896 + h * 112 + d];
    }
    for (int k = tid; k < NKEYS; k += 256) {
        size_t o;
        if (k < 8)       { o = ((size_t)(b * 8 + k)) * 896 + h * 112;          kp[k] = g_Ks + o; vp[k] = g_Vs + o; }
        else if (k < 73) { o = ((size_t)(b * 65 + (k - 8))) * 896 + h * 112;   kp[k] = g_Ka + o; vp[k] = g_Va + o; }
        else             { o = ((size_t)(b * 512 + (k - 73))) * 896 + h * 112; kp[k] = g_Kt + o; }
    }
    __syncthreads();

    const float ratio = tanhf(gate[0]);
    const float sc0   = rsqrtf(112.0f);

    for (int k = tid; k < NKEYS; k += 256) {
        const __half* kb = kp[k];
        float acc[8] = {0.f, 0.f, 0.f, 0.f, 0.f, 0.f, 0.f, 0.f};
        #pragma unroll 2
        for (int d8 = 0; d8 < 14; ++d8) {
            uint4 raw = *(const uint4*)(kb + d8 * 8);
            const __half2* hp = (const __half2*)&raw;
            float2 f0 = __half22float2(hp[0]);
            float2 f1 = __half22float2(hp[1]);
            float2 f2 = __half22float2(hp[2]);
            float2 f3 = __half22float2(hp[3]);
            #pragma unroll
            for (int r = 0; r < 8; r++) {
                const float* q = &q_s[r][d8 * 8];
                acc[r] = fmaf(q[0], f0.x, acc[r]);
                acc[r] = fmaf(q[1], f0.y, acc[r]);
                acc[r] = fmaf(q[2], f1.x, acc[r]);
                acc[r] = fmaf(q[3], f1.y, acc[r]);
                acc[r] = fmaf(q[4], f2.x, acc[r]);
                acc[r] = fmaf(q[5], f2.y, acc[r]);
                acc[r] = fmaf(q[6], f3.x, acc[r]);
                acc[r] = fmaf(q[7], f3.y, acc[r]);
            }
        }
        float sc = (k < 73) ? sc0 : sc0 * ratio;
        #pragma unroll
        for (int r = 0; r < 8; r++) w_s[r][k] = acc[r] * sc;
    }
    __syncthreads();

    // softmax (one warp per query row) + task weight-sum
    {
        int r = tid >> 5, lane = tid & 31;
        float m = -3.0e38f;
        for (int k = lane; k < NKEYS; k += 32) m = fmaxf(m, w_s[r][k]);
        #pragma unroll
        for (int o = 16; o; o >>= 1) m = fmaxf(m, __shfl_xor_sync(0xffffffffu, m, o));
        float s = 0.0f;
        for (int k = lane; k < NKEYS; k += 32) { float e = __expf(w_s[r][k] - m); w_s[r][k] = e; s += e; }
        #pragma unroll
        for (int o = 16; o; o >>= 1) s += __shfl_xor_sync(0xffffffffu, s, o);
        float inv = 1.0f / s;
        for (int k = lane; k < NKEYS; k += 32) w_s[r][k] *= inv;
        float sv = 0.0f;
        for (int k = 73 + lane; k < NKEYS; k += 32) sv += w_s[r][k];
        #pragma unroll
        for (int o = 16; o; o >>= 1) sv += __shfl_xor_sync(0xffffffffu, sv, o);
        if (lane == 0) g_st[(b * 8 + h) * 8 + r] = sv;
    }
    __syncthreads();

    // export task weights fp16: [b][(h*8+t)][512]
    for (int i = tid; i < 8 * 512; i += 256) {
        int t = i >> 9, k = i & 511;
        g_wt[((size_t)b * 64 + h * 8 + t) * 512 + k] = __float2half_rn(w_s[t][73 + k]);
    }

    // self + ad partial AV (73 keys)
    for (int idx = tid; idx < 896; idx += 256) {
        int r = idx / 112, d = idx % 112;
        float acc = 0.0f;
        #pragma unroll 4
        for (int k = 0; k < 73; k++) acc = fmaf(w_s[r][k], __half2float(vp[k][d]), acc);
        g_oPart[((size_t)(b * 8 + h) * 8 + r) * 112 + d] = acc;
    }
}

// ==================== wsum GEMM: w_t[b](64x512) @ h_t[b](512x896) ===========
// grid = (b, ncol): 64*7 CTAs. M=64, N=128, K=512. B is k-major -> ldmatrix.trans.
#define WS_LDA 40    // halves
#define WS_LDB 136   // halves
__global__ __launch_bounds__(256, 2) void wsum_k()
{
    __shared__ __half sA[2][64 * WS_LDA];
    __shared__ __half sB[2][32 * WS_LDB];
    const int bb = blockIdx.x / 7;
    const int col0 = (blockIdx.x % 7) * 128;
    const int tid = threadIdx.x, lane = tid & 31, wid = tid >> 5;
    const int wmi = wid >> 2, wni = wid & 3;

    const __half* Aw = g_wt  + (size_t)bb * 64 * 512;
    const __half* Bh = g_hth + (size_t)bb * 512 * 896 + col0;

    float acc[2][4][4];
    #pragma unroll
    for (int mi = 0; mi < 2; mi++)
        #pragma unroll
        for (int nj = 0; nj < 4; nj++)
            #pragma unroll
            for (int q = 0; q < 4; q++) acc[mi][nj][q] = 0.0f;

    // ldmatrix.trans lane addressing for B [k][n] tiles
    const int bt_k = (lane % 8) + (lane & 8);
    const int bt_n = (lane & 16) >> 1;

    // stage 0 load
    {
        int r = tid >> 2, c = tid & 3;
        CP_ASYNC16(smem_u32(&sA[0][r * WS_LDA + c * 8]), Aw + r * 512 + c * 8);
        #pragma unroll
        for (int i = 0; i < 2; i++) {
            int cc = i * 256 + tid;
            int rr = cc >> 4, cx = cc & 15;
            CP_ASYNC16(smem_u32(&sB[0][rr * WS_LDB + cx * 8]), Bh + (size_t)rr * 896 + cx * 8);
        }
        CP_COMMIT();
    }

    #pragma unroll 1
    for (int t = 0; t < 16; t++) {
        CP_WAIT0();
        __syncthreads();
        if (t + 1 < 16) {
            int st = (t + 1) & 1, kt = (t + 1) * 32;
            int r = tid >> 2, c = tid & 3;
            CP_ASYNC16(smem_u32(&sA[st][r * WS_LDA + c * 8]), Aw + r * 512 + kt + c * 8);
            #pragma unroll
            for (int i = 0; i < 2; i++) {
                int cc = i * 256 + tid;
                int rr = cc >> 4, cx = cc & 15;
                CP_ASYNC16(smem_u32(&sB[st][rr * WS_LDB + cx * 8]), Bh + (size_t)(kt + rr) * 896 + cx * 8);
            }
            CP_COMMIT();
        }
        const int buf = t & 1;
        #pragma unroll
        for (int ks = 0; ks < 2; ks++) {
            uint32_t a[2][4], bf[4][2];
            #pragma unroll
            for (int mi = 0; mi < 2; mi++) {
                uint32_t aaddr = smem_u32(&sA[buf][(wmi * 32 + mi * 16 + (lane & 15)) * WS_LDA])
                                 + ((lane >> 4) * 16) + ks * 32;
                LDSM4(a[mi][0], a[mi][1], a[mi][2], a[mi][3], aaddr);
            }
            #pragma unroll
            for (int nb = 0; nb < 2; nb++) {
                uint32_t baddr = smem_u32(&sB[buf][(ks * 16 + bt_k) * WS_LDB
                                  + wni * 32 + nb * 16 + bt_n]);
                LDSM4_T(bf[2*nb][0], bf[2*nb][1], bf[2*nb+1][0], bf[2*nb+1][1], baddr);
            }
            #pragma unroll
            for (int mi = 0; mi < 2; mi++)
                #pragma unroll
                for (int nj = 0; nj < 4; nj++)
                    MMA_F16(acc[mi][nj], a[mi], bf[nj][0], bf[nj][1]);
        }
        __syncthreads();
    }

    // epilogue -> g_wsum fp16
    #pragma unroll
    for (int mi = 0; mi < 2; mi++) {
        #pragma unroll
        for (int half = 0; half < 2; half++) {
            int r = wmi * 32 + mi * 16 + (lane >> 2) + half * 8;   // 0..63
            __half* crow = g_wsum + ((size_t)bb * 64 + r) * 896;
            #pragma unroll
            for (int nj = 0; nj < 4; nj++) {
                int gc = col0 + wni * 32 + nj * 8 + (lane & 3) * 2;
                __half2 h2 = __floats2half2_rn(acc[mi][nj][half * 2], acc[mi][nj][half * 2 + 1]);
                *(uint32_t*)(crow + gc) = *(uint32_t*)&h2;
            }
        }
    }
}

// ==================== proj: per-head wsum @ Wvt[:,h*112:+112] + combine =====
// grid = 32: (h = blk>>2, mt = blk&3). M=128 rows of (b,t), N=128 (112 valid), K=896.
__global__ __launch_bounds__(256, 2) void proj_k(const float* __restrict__ bvt)
{
    extern __shared__ __align__(128) char smx[];
    const int h  = blockIdx.x >> 2;
    const int mt = blockIdx.x & 3;
    const int tid  = threadIdx.x;
    const int lane = tid & 31, wid = tid >> 5;
    const int wm = (wid & 3) * 32, wn = (wid >> 2) * 64;
    uint32_t sb = smem_u32(smx);

    const __half* Bb = (const __half*)g_W + (size_t)6 * 896 * 896 + (size_t)(h * 112) * 896;

    float acc[2][8][4];
    #pragma unroll
    for (int mi = 0; mi < 2; mi++)
        #pragma unroll
        for (int nj = 0; nj < 8; nj++)
            #pragma unroll
            for (int q = 0; q < 4; q++) acc[mi][nj][q] = 0.0f;

    const int a_r = lane & 15;
    const int a_k = (lane >> 4) * 16;
    const int b_r = (lane & 7) + ((lane >> 4) & 1) * 8;
    const int b_k = ((lane >> 3) & 1) * 16;

    auto load_st = [&](uint32_t s0, int kt) {
        #pragma unroll
        for (int i = 0; i < 4; i++) {
            const int sel = i >> 1;
            int cc = (i & 1) * 256 + tid;
            int r = cc >> 2, ks = cc & 3;
            uint32_t dst = s0 + (uint32_t)sel * 10240u + (uint32_t)(r * LDAB + ks * 16);
            if (sel == 0) {
                int rr = mt * 128 + r;
                int grow = ((rr >> 3) << 6) + h * 8 + (rr & 7);
                CP_ASYNC16(dst, g_wsum + (size_t)grow * 896 + kt + ks * 8);
            } else {
                CP_ASYNC16(dst, Bb + (size_t)r * 896 + kt + ks * 8);
            }
        }
    };

    load_st(sb, 0);
    CP_COMMIT();
    load_st(sb + STAGE_B, 32);
    CP_COMMIT();

    #pragma unroll 1
    for (int t = 0; t < 28; t++) {
        CP_WAIT1();
        __syncthreads();
        if (t + 2 < 28)
            load_st(sb + ((t + 2) % 3) * STAGE_B, (t + 2) * 32);
        CP_COMMIT();

        uint32_t s0 = sb + (t % 3) * STAGE_B;
        uint32_t aB = s0 +         (uint32_t)((wm + a_r) * LDAB + a_k);
        uint32_t bB = s0 + 10240 + (uint32_t)((wn + b_r) * LDAB + b_k);
        #pragma unroll
        for (int ks = 0; ks < 2; ks++) {
            const uint32_t ksb = ks * 32;
            uint32_t a[2][4], bh[8][2];
            #pragma unroll
            for (int mi = 0; mi < 2; mi++)
                LDSM4(a[mi][0], a[mi][1], a[mi][2], a[mi][3], aB + mi * (16 * LDAB) + ksb);
            #pragma unroll
            for (int p = 0; p < 4; p++)
                LDSM4(bh[2*p][0], bh[2*p][1], bh[2*p+1][0], bh[2*p+1][1], bB + p * (16 * LDAB) + ksb);
            #pragma unroll
            for (int mi = 0; mi < 2; mi++)
                #pragma unroll
                for (int nj = 0; nj < 8; nj++)
                    MMA_F16(acc[mi][nj], a[mi], bh[nj][0], bh[nj][1]);
        }
    }

    // epilogue: add self/ad partial + weighted bias, write ath (fp16)
    #pragma unroll
    for (int mi = 0; mi < 2; mi++) {
        #pragma unroll
        for (int half = 0; half < 2; half++) {
            int rr = mt * 128 + wm + mi * 16 + (lane >> 2) + half * 8;   // 0..511
            int bq = rr >> 3, tq = rr & 7;
            float stv = g_st[(bq * 8 + h) * 8 + tq];
            const float* op = g_oPart + ((size_t)(bq * 8 + h) * 8 + tq) * 112;
            __half* crow = g_ath + ((size_t)(bq * 8 + tq)) * 896 + h * 112;
            #pragma unroll
            for (int nj = 0; nj < 8; nj++) {
                int gc = wn + nj * 8 + (lane & 3) * 2;
                if (gc >= 112) continue;
                float v0 = acc[mi][nj][half * 2]     + op[gc]     + stv * bvt[h * 112 + gc];
                float v1 = acc[mi][nj][half * 2 + 1] + op[gc + 1] + stv * bvt[h * 112 + gc + 1];
                __half2 h2 = __floats2half2_rn(v0, v1);
                *(uint32_t*)(crow + gc) = *(uint32_t*)&h2;
            }
        }
    }
}

// ==================== layernorm (emits fp16) ================================
__global__ __launch_bounds__(256) void ln_k(const float* __restrict__ g,
                                            const float* __restrict__ bt)
{
    int row = blockIdx.x;
    const float* y = g_y + (size_t)row * 896;
    int tid = threadIdx.x;
    float s = 0.0f, s2 = 0.0f;
    for (int j = tid; j < 896; j += 256) { float v = y[j]; s += v; s2 += v * v; }
    __shared__ float rs[8], rs2[8];
    #pragma unroll
    for (int o = 16; o; o >>= 1) { s += __shfl_xor_sync(~0u, s, o); s2 += __shfl_xor_sync(~0u, s2, o); }
    if ((tid & 31) == 0) { rs[tid >> 5] = s; rs2[tid >> 5] = s2; }
    __syncthreads();
    if (tid < 32) {
        s  = (tid < 8) ? rs[tid]  : 0.0f;
        s2 = (tid < 8) ? rs2[tid] : 0.0f;
        #pragma unroll
        for (int o = 4; o; o >>= 1) { s += __shfl_xor_sync(~0u, s, o); s2 += __shfl_xor_sync(~0u, s2, o); }
        if (tid == 0) { rs[0] = s; rs2[0] = s2; }
    }
    __syncthreads();
    float mu  = rs[0]  * (1.0f / 896.0f);
    float var = rs2[0] * (1.0f / 896.0f) - mu * mu;
    float inv = rsqrtf(var + 1e-5f);
    for (int j = tid; j < 896; j += 256)
        g_ynh[(size_t)row * 896 + j] = __float2half_rn((y[j] - mu) * inv * g[j] + bt[j]);
}

// ==================== host orchestration ====================================
extern "C" void kernel_launch(void* const* d_in, const int* in_sizes, int n_in,
                              void* d_out, int out_size)
{
    const float* x   = (const float*)d_in[0];
    const float* h_a = (const float*)d_in[1];
    const float* h_t = (const float*)d_in[2];
    const float* p   = (const float*)d_in[3];
    const float* Wq  = (const float*)d_in[4],  *bq  = (const float*)d_in[5];
    const float* Wks = (const float*)d_in[6],  *bks = (const float*)d_in[7];
    const float* Wvs = (const float*)d_in[8],  *bvs = (const float*)d_in[9];
    const float* Wka = (const float*)d_in[10], *bka = (const float*)d_in[11];
    const float* Wva = (const float*)d_in[12], *bva = (const float*)d_in[13];
    const float* Wkt = (const float*)d_in[14], *bkt = (const float*)d_in[15];
    const float* Wvt = (const float*)d_in[16], *bvt = (const float*)d_in[17];
    const float* Wo  = (const float*)d_in[18], *bo  = (const float*)d_in[19];
    const float* Wf  = (const float*)d_in[20], *bf  = (const float*)d_in[21];
    const float* gate = (const float*)d_in[22];
    const float* ln_g = (const float*)d_in[23];
    const float* ln_b = (const float*)d_in[24];

    float *Q, *y;
    __half *Ks, *Vs, *Ka, *Va, *Kt;
    __half *W, *xh, *hadh, *hth, *ath, *ynh;
    cudaGetSymbolAddress((void**)&Q,    g_Q);
    cudaGetSymbolAddress((void**)&Ks,   g_Ks);
    cudaGetSymbolAddress((void**)&Vs,   g_Vs);
    cudaGetSymbolAddress((void**)&Ka,   g_Ka);
    cudaGetSymbolAddress((void**)&Va,   g_Va);
    cudaGetSymbolAddress((void**)&Kt,   g_Kt);
    cudaGetSymbolAddress((void**)&y,    g_y);
    cudaGetSymbolAddress((void**)&W,    g_W);
    cudaGetSymbolAddress((void**)&xh,   g_xh);
    cudaGetSymbolAddress((void**)&hadh, g_hadh);
    cudaGetSymbolAddress((void**)&hth,  g_hth);
    cudaGetSymbolAddress((void**)&ath,  g_ath);
    cudaGetSymbolAddress((void**)&ynh,  g_ynh);

    cudaFuncSetAttribute(wgemm_k, cudaFuncAttributeMaxDynamicSharedMemorySize, SM_TOTAL);
    cudaFuncSetAttribute(proj_k,  cudaFuncAttributeMaxDynamicSharedMemorySize, SM_TOTAL);

    rope_init_k<<<(512 * 112 + 255) / 256, 256>>>();

    WPtrs wp;
    wp.w[0] = Wq; wp.w[1] = Wks; wp.w[2] = Wvs; wp.w[3] = Wka; wp.w[4] = Wva;
    wp.w[5] = Wkt; wp.w[6] = Wvt; wp.w[7] = Wo; wp.w[8] = Wf;
    convw_k<<<dim3(28, 28, 9), dim3(32, 8)>>>(wp);

    cvt_k<<<(512 * 224 + 255) / 256, 256>>>(x, xh, 512 * 224);
    cvt_k<<<(32768 * 224 + 255) / 256, 256>>>(h_t, hth, 32768 * 224);
    build_had_k<<<(4224 * 224 + 255) / 256, 256>>>(h_a, p);

    const size_t WS = 896 * 896;

    // ---- batched GEMM: Kt (1792) + Ka/Va (462) + QKV (84) ------------------
    {
        GB3 gb;
        gb.g[0].Ah = hth; gb.g[0].B = W + 5 * WS;
        gb.g[0].M = 32768; gb.g[0].ncol = 7;
        gb.g[0].out[0] = Kt; gb.g[0].bias[0] = bkt; gb.g[0].epi[0] = 1; gb.g[0].rl[0] = 512; gb.g[0].hout[0] = 1;
        gb.g[0].out[1] = nullptr; gb.g[0].bias[1] = nullptr; gb.g[0].epi[1] = 0; gb.g[0].rl[1] = 1; gb.g[0].hout[1] = 0;
        gb.g[0].out[2] = nullptr; gb.g[0].bias[2] = nullptr; gb.g[0].epi[2] = 0; gb.g[0].rl[2] = 1; gb.g[0].hout[2] = 0;
        gb.g[0].res = nullptr;

        gb.g[1].Ah = hadh; gb.g[1].B = W + 3 * WS;
        gb.g[1].M = 4160; gb.g[1].ncol = 14;
        gb.g[1].out[0] = Ka; gb.g[1].bias[0] = bka; gb.g[1].epi[0] = 1; gb.g[1].rl[0] = 65; gb.g[1].hout[0] = 1;
        gb.g[1].out[1] = Va; gb.g[1].bias[1] = bva; gb.g[1].epi[1] = 0; gb.g[1].rl[1] = 1;  gb.g[1].hout[1] = 1;
        gb.g[1].out[2] = nullptr; gb.g[1].bias[2] = nullptr; gb.g[1].epi[2] = 0; gb.g[1].rl[2] = 1; gb.g[1].hout[2] = 0;
        gb.g[1].res = nullptr;

        gb.g[2].Ah = xh; gb.g[2].B = W;
        gb.g[2].M = 512; gb.g[2].ncol = 21;
        gb.g[2].out[0] = Q;  gb.g[2].bias[0] = bq;  gb.g[2].epi[0] = 1; gb.g[2].rl[0] = 8; gb.g[2].hout[0] = 0;
        gb.g[2].out[1] = Ks; gb.g[2].bias[1] = bks; gb.g[2].epi[1] = 1; gb.g[2].rl[1] = 8; gb.g[2].hout[1] = 1;
        gb.g[2].out[2] = Vs; gb.g[2].bias[2] = bvs; gb.g[2].epi[2] = 0; gb.g[2].rl[2] = 1; gb.g[2].hout[2] = 1;
        gb.g[2].res = nullptr;
        gb.b0 = 1792; gb.b1 = 1792 + 462;
        wgemm_k<<<1792 + 462 + 84, 256, SM_TOTAL>>>(gb);
    }

    attn_k<<<512, 256>>>(gate);
    wsum_k<<<64 * 7, 256>>>();
    proj_k<<<32, 256, SM_TOTAL>>>(bvt);

    // ---- Wo: +bias +residual(x) -> y ---------------------------------------
    {
        GB3 gb;
        gb.g[0].Ah = ath; gb.g[0].B = W + 7 * WS;
        gb.g[0].M = 512; gb.g[0].ncol = 7;
        gb.g[0].out[0] = y; gb.g[0].bias[0] = bo; gb.g[0].epi[0] = 2; gb.g[0].rl[0] = 1; gb.g[0].hout[0] = 0;
        gb.g[0].out[1] = nullptr; gb.g[0].bias[1] = nullptr; gb.g[0].epi[1] = 0; gb.g[0].rl[1] = 1; gb.g[0].hout[1] = 0;
        gb.g[0].out[2] = nullptr; gb.g[0].bias[2] = nullptr; gb.g[0].epi[2] = 0; gb.g[0].rl[2] = 1; gb.g[0].hout[2] = 0;
        gb.g[0].res = x;
        gb.g[1] = gb.g[0]; gb.g[2] = gb.g[0];
        gb.b0 = 1 << 30; gb.b1 = 1 << 30;
        wgemm_k<<<28, 256, SM_TOTAL>>>(gb);
    }

    ln_k<<<512, 256>>>(ln_g, ln_b);

    // ---- Wf: +bias, ReLU -> d_out ------------------------------------------
    {
        GB3 gb;
        gb.g[0].Ah = ynh; gb.g[0].B = W + 8 * WS;
        gb.g[0].M = 512; gb.g[0].ncol = 7;
        gb.g[0].out[0] = d_out; gb.g[0].bias[0] = bf; gb.g[0].epi[0] = 3; gb.g[0].rl[0] = 1; gb.g[0].hout[0] = 0;
        gb.g[0].out[1] = nullptr; gb.g[0].bias[1] = nullptr; gb.g[0].epi[1] = 0; gb.g[0].rl[1] = 1; gb.g[0].hout[1] = 0;
        gb.g[0].out[2] = nullptr; gb.g[0].bias[2] = nullptr; gb.g[0].epi[2] = 0; gb.g[0].rl[2] = 1; gb.g[0].hout[2] = 0;
        gb.g[0].res = nullptr;
        gb.g[1] = gb.g[0]; gb.g[2] = gb.g[0];
        gb.b0 = 1 << 30; gb.b1 = 1 << 30;
        wgemm_k<<<28, 256, SM_TOTAL>>>(gb);
    }
}